// round 11
// baseline (speedup 1.0000x reference)
#include <cuda_runtime.h>
#include <cuda_fp16.h>
#include <math.h>
#include <stdint.h>

#define BB 4
#define SS 1024
#define DD 1024
#define HH 16
#define DHH 64
#define FFD 4096
#define LL 4
#define PP 1024
#define SPAN_ 512
#define BS (BB*SS)

typedef long long ll;
typedef __half hf;

// ---------------- scratch ------------------------------------------------------
__device__ float g_h [BS*DD];
__device__ float g_t2[BS*DD];
__device__ float qkv_bias[4*3*DD];
__device__ float pos_bias[4*2*DD];

__device__ hf hb    [BS*DD];
__device__ hf qkvb  [(size_t)BS*3*DD];
__device__ hf cxb   [BS*DD];
__device__ hf ffb   [(size_t)BS*FFD];
__device__ hf rlb   [PP*DD];
__device__ hf posb  [(size_t)PP*2*DD];
__device__ hf wqkvt [(size_t)4*3*DD*DD];
__device__ hf wpost [(size_t)4*2*DD*DD];
__device__ hf wot   [(size_t)4*DD*DD];
__device__ hf w1t   [(size_t)4*FFD*DD];
__device__ hf w2t   [(size_t)4*DD*FFD];
__device__ hf vtb   [(size_t)BB*HH*DHH*SS];
__device__ hf prb   [(size_t)BB*HH*SS*SS];
__device__ hf s1b   [(size_t)BB*HH*SS*SS];
__device__ hf c2pb  [(size_t)BB*HH*SS*PP];
__device__ hf Fb_   [(size_t)BB*HH*2048*SS];   // skewed p2c: F[bh][p+k][k]

// ---------------- helpers ------------------------------------------------------
__device__ __forceinline__ uint32_t smem_u32(const void* p) {
    uint32_t a;
    asm("{ .reg .u64 t; cvta.to.shared.u64 t, %1; cvt.u32.u64 %0, t; }" : "=r"(a) : "l"(p));
    return a;
}
__device__ __forceinline__ void cpa16(uint32_t dst, const void* src) {
    asm volatile("cp.async.cg.shared.global [%0], [%1], 16;" :: "r"(dst), "l"(src));
}
__device__ __forceinline__ void cpa_commit() { asm volatile("cp.async.commit_group;" ::: "memory"); }

__device__ __forceinline__ void ldm4(uint32_t* r, uint32_t addr) {
    asm volatile("ldmatrix.sync.aligned.m8n8.x4.shared.b16 {%0,%1,%2,%3}, [%4];"
                 : "=r"(r[0]), "=r"(r[1]), "=r"(r[2]), "=r"(r[3]) : "r"(addr));
}
__device__ __forceinline__ void mma16816(float* d, const uint32_t* a, const uint32_t* b) {
    asm volatile("mma.sync.aligned.m16n8k16.row.col.f32.f16.f16.f32 "
                 "{%0,%1,%2,%3}, {%4,%5,%6,%7}, {%8,%9}, {%0,%1,%2,%3};"
                 : "+f"(d[0]), "+f"(d[1]), "+f"(d[2]), "+f"(d[3])
                 : "r"(a[0]), "r"(a[1]), "r"(a[2]), "r"(a[3]), "r"(b[0]), "r"(b[1]));
}

// ---------------- fp16 mma.sync GEMM, 3-stage, 1 sync/chunk ----------------------
// SKEW=0: normal epilogue (C fp32 and/or Ch fp16).
// SKEW=1: Ch = F base; writes F[(z*2048 + p + k)][k] via SMEM anti-diagonal staging.
template <int NT, int ACT, int SKEW>
__global__ void __launch_bounds__(256) gemm_mma(
    const hf* __restrict__ A, int ldA, ll aSB, ll aSH,
    const hf* __restrict__ B, int ldB, ll bSB, ll bSH,
    float* __restrict__ C, hf* __restrict__ Ch,
    int ldC, ll cSB, ll cSH,
    int K, const float* __restrict__ bias)
{
    constexpr int ABY = 128 * 128;
    constexpr int BBY = NT * 128;
    constexpr int STAGE = ABY + BBY;
    constexpr int MT = (NT == 128) ? 4 : 2;
    constexpr int JT = 4;

    extern __shared__ char smem_raw[];
    uint32_t sbase = smem_u32(smem_raw);

    int tid = threadIdx.x, lane = tid & 31, wid = tid >> 5;
    int z = blockIdx.z;

    int warpM, warpN;
    if (NT == 128) { warpM = (wid & 1) * 64; warpN = (wid >> 1) * 32; }
    else           { warpM = (wid & 3) * 32; warpN = (wid >> 2) * 32; }

    const hf* Ab = A + (size_t)((ll)(z >> 4) * aSB + (ll)(z & 15) * aSH)
                     + (size_t)blockIdx.y * 128 * ldA;
    const hf* Bb = B + (size_t)((ll)(z >> 4) * bSB + (ll)(z & 15) * bSH)
                     + (size_t)blockIdx.x * NT * ldB;

    int NC = K >> 6;

    auto load_chunk = [&](int cn, int stage) {
        const hf* Ap = Ab + cn * 64;
        const hf* Bp = Bb + cn * 64;
        uint32_t Ad = sbase + stage * STAGE;
        uint32_t Bd = Ad + ABY;
        #pragma unroll
        for (int i = 0; i < 4; i++) {
            int idx = tid + i * 256;
            int r = idx >> 3, c = idx & 7;
            cpa16(Ad + r * 128 + ((c ^ (r & 7)) << 4), Ap + (size_t)r * ldA + c * 8);
        }
        #pragma unroll
        for (int i = 0; i < NT / 32; i++) {
            int idx = tid + i * 256;
            int r = idx >> 3, c = idx & 7;
            cpa16(Bd + r * 128 + ((c ^ (r & 7)) << 4), Bp + (size_t)r * ldB + c * 8);
        }
        cpa_commit();
    };

    float acc[MT][JT][4];
    #pragma unroll
    for (int i = 0; i < MT; i++)
        #pragma unroll
        for (int j = 0; j < JT; j++)
            #pragma unroll
            for (int e = 0; e < 4; e++) acc[i][j][e] = 0.f;

    load_chunk(0, 0);
    if (NC > 1) load_chunk(1, 1);

    for (int c = 0; c < NC; c++) {
        if (c + 1 < NC) asm volatile("cp.async.wait_group 1;" ::: "memory");
        else            asm volatile("cp.async.wait_group 0;" ::: "memory");
        __syncthreads();

        uint32_t Abuf = sbase + (c % 3) * STAGE;
        uint32_t Bbuf = Abuf + ABY;
        #pragma unroll
        for (int ks = 0; ks < 4; ks++) {
            uint32_t a[MT][4], b[JT][2];
            #pragma unroll
            for (int i = 0; i < MT; i++) {
                int row = warpM + i * 16 + (lane & 15);
                int cc = ks * 2 + (lane >> 4);
                ldm4(a[i], Abuf + row * 128 + (((cc ^ (row & 7)) << 4)));
            }
            #pragma unroll
            for (int j = 0; j < JT / 2; j++) {
                int n = warpN + j * 16 + ((lane >> 4) << 3) + (lane & 7);
                int cc = ks * 2 + ((lane >> 3) & 1);
                uint32_t t[4];
                ldm4(t, Bbuf + n * 128 + (((cc ^ (n & 7)) << 4)));
                b[j*2][0] = t[0];   b[j*2][1] = t[1];
                b[j*2+1][0] = t[2]; b[j*2+1][1] = t[3];
            }
            #pragma unroll
            for (int i = 0; i < MT; i++)
                #pragma unroll
                for (int j = 0; j < JT; j++)
                    mma16816(acc[i][j], a[i], b[j]);
        }
        if (c + 2 < NC) load_chunk(c + 2, (c + 2) % 3);
    }

    int quad = lane >> 2, l4 = lane & 3;

    if (SKEW) {
        // stage anti-diagonal rows: T[(k_local+p_local)][k_local]
        __syncthreads();
        hf* T = (hf*)smem_raw;
        #pragma unroll
        for (int i = 0; i < MT; i++)
            #pragma unroll
            for (int j = 0; j < JT; j++)
                #pragma unroll
                for (int half = 0; half < 2; half++) {
                    int kl = warpM + i * 16 + quad + half * 8;
                    #pragma unroll
                    for (int e = 0; e < 2; e++) {
                        int pl = warpN + j * 8 + l4 * 2 + e;
                        T[(kl + pl) * 128 + kl] = __float2half(acc[i][j][half*2 + e]);
                    }
                }
        __syncthreads();
        int k0 = blockIdx.y * 128, p0 = blockIdx.x * 128;
        hf* F = Ch + (size_t)z * 2048 * SS;
        size_t rowBase = (size_t)(k0 + p0) * SS + k0;
        for (int r = wid; r < 255; r += 8) {
            int klo = max(0, r - 127), khi = min(127, r);
            for (int cc = klo + lane; cc <= khi; cc += 32)
                F[rowBase + (size_t)r * SS + cc] = T[r * 128 + cc];
        }
        return;
    }

    ll cO = (ll)(z >> 4) * cSB + (ll)(z & 15) * cSH;
    int m0 = blockIdx.y * 128, n0 = blockIdx.x * NT;

    #pragma unroll
    for (int i = 0; i < MT; i++) {
        int r0 = m0 + warpM + i * 16 + quad;
        #pragma unroll
        for (int j = 0; j < JT; j++) {
            int col = n0 + warpN + j * 8 + l4 * 2;
            float b0 = 0.f, b1 = 0.f;
            if (bias) { b0 = bias[col]; b1 = bias[col + 1]; }
            #pragma unroll
            for (int half = 0; half < 2; half++) {
                int row = r0 + half * 8;
                float v0 = acc[i][j][half*2 + 0] + b0;
                float v1 = acc[i][j][half*2 + 1] + b1;
                if (ACT) {
                    v0 = 0.5f * v0 * (1.f + erff(v0 * 0.70710678118654752f));
                    v1 = 0.5f * v1 * (1.f + erff(v1 * 0.70710678118654752f));
                }
                size_t base = (size_t)cO + (size_t)row * ldC + col;
                if (C) *(float2*)(C + base) = make_float2(v0, v1);
                if (Ch) *(__half2*)(Ch + base) =
                    __halves2half2(__float2half(v0), __float2half(v1));
            }
        }
    }
}

// ---------------- converters -----------------------------------------------------
__global__ __launch_bounds__(256) void cvt_fp16(
    const float* __restrict__ in, hf* __restrict__ out, size_t n)
{
    for (size_t i = blockIdx.x * 256ull + threadIdx.x; i < n; i += gridDim.x * 256ull)
        out[i] = __float2half(in[i]);
}

__global__ void concat_bias(const float* bq, const float* bk, const float* bv,
                            float* out2, float* out3)
{
    int l = blockIdx.z;
    const float* a = bq + (size_t)l * DD;
    const float* b = bk + (size_t)l * DD;
    const float* c = bv + (size_t)l * DD;
    float* o3 = out3 + (size_t)l * 3 * DD;
    float* o2 = out2 + (size_t)l * 2 * DD;
    int i = blockIdx.x * 256 + threadIdx.x;
    if (i < DD) {
        o3[i] = a[i]; o3[i + DD] = b[i]; o3[i + 2*DD] = c[i];
        o2[i] = b[i]; o2[i + DD] = a[i];
    }
}

__global__ void transpose_cvt(
    const float* __restrict__ in, ll inLS, hf* __restrict__ out, ll outLS,
    int K, int N)
{
    in  += (size_t)blockIdx.z * inLS;
    out += (size_t)blockIdx.z * outLS;
    __shared__ float t[32][33];
    int k0 = blockIdx.y * 32, n0 = blockIdx.x * 32;
    int tx = threadIdx.x, ty = threadIdx.y;
    for (int i = ty; i < 32; i += 8)
        t[i][tx] = in[(size_t)(k0 + i) * N + n0 + tx];
    __syncthreads();
    for (int i = ty; i < 32; i += 8)
        out[(size_t)(n0 + i) * K + k0 + tx] = __float2half(t[tx][i]);
}

__global__ void vt_cvt(const hf* __restrict__ v, int ldv, hf* __restrict__ out)
{
    __shared__ hf t[32][33];
    int bh = blockIdx.z, b = bh >> 4, h = bh & 15;
    int s0 = blockIdx.x * 32, d0 = blockIdx.y * 32;
    int tx = threadIdx.x, ty = threadIdx.y;
    for (int i = ty; i < 32; i += 8)
        t[i][tx] = v[((size_t)b * SS + s0 + i) * ldv + h * 64 + d0 + tx];
    __syncthreads();
    for (int i = ty; i < 32; i += 8)
        out[((size_t)bh * 64 + d0 + i) * SS + s0 + tx] = t[tx][i];
}

// ---------------- embedding / LN ----------------------------------------------
__global__ __launch_bounds__(256) void embed_ln(
    const int* __restrict__ ids, const int* __restrict__ segs,
    const float* __restrict__ mask, const float* __restrict__ tok,
    const float* __restrict__ seg, const float* __restrict__ g,
    const float* __restrict__ b)
{
    int row = blockIdx.x, tid = threadIdx.x;
    const float* t  = tok + (size_t)ids[row]  * DD;
    const float* sg = seg + (size_t)segs[row] * DD;
    float x[4]; float s = 0.f;
    #pragma unroll
    for (int i = 0; i < 4; i++) { int c = tid + i*256; x[i] = t[c] + sg[c]; s += x[i]; }
    __shared__ float red[256];
    red[tid] = s; __syncthreads();
    for (int o = 128; o > 0; o >>= 1) { if (tid < o) red[tid] += red[tid+o]; __syncthreads(); }
    float m = red[0] * (1.f / DD); __syncthreads();
    s = 0.f;
    #pragma unroll
    for (int i = 0; i < 4; i++) { float d = x[i] - m; s += d*d; }
    red[tid] = s; __syncthreads();
    for (int o = 128; o > 0; o >>= 1) { if (tid < o) red[tid] += red[tid+o]; __syncthreads(); }
    float inv = rsqrtf(red[0] * (1.f / DD) + 1e-12f);
    float mk = mask[row];
    #pragma unroll
    for (int i = 0; i < 4; i++) {
        int c = tid + i*256;
        float y = ((x[i] - m) * inv * g[c] + b[c]) * mk;
        size_t o = (size_t)row * DD + c;
        g_h[o] = y; hb[o] = __float2half(y);
    }
}

__global__ __launch_bounds__(256) void add_ln(
    const float* __restrict__ base, const float* __restrict__ addv,
    const float* __restrict__ g, const float* __restrict__ b,
    float* __restrict__ out)
{
    int row = blockIdx.x, tid = threadIdx.x;
    size_t off = (size_t)row * DD;
    float x[4]; float s = 0.f;
    #pragma unroll
    for (int i = 0; i < 4; i++) { int c = tid + i*256; x[i] = base[off+c] + addv[off+c]; s += x[i]; }
    __shared__ float red[256];
    red[tid] = s; __syncthreads();
    for (int o = 128; o > 0; o >>= 1) { if (tid < o) red[tid] += red[tid+o]; __syncthreads(); }
    float m = red[0] * (1.f / DD); __syncthreads();
    s = 0.f;
    #pragma unroll
    for (int i = 0; i < 4; i++) { float d = x[i] - m; s += d*d; }
    red[tid] = s; __syncthreads();
    for (int o = 128; o > 0; o >>= 1) { if (tid < o) red[tid] += red[tid+o]; __syncthreads(); }
    float inv = rsqrtf(red[0] * (1.f / DD) + 1e-12f);
    #pragma unroll
    for (int i = 0; i < 4; i++) {
        int c = tid + i*256;
        float y = (x[i] - m) * inv * g[c] + b[c];
        out[off + c] = y; hb[off + c] = __float2half(y);
    }
}

// ---------------- warp-per-row softmax, skewed p2c read ------------------------
__global__ __launch_bounds__(256) void softmax_rel(
    const hf* __restrict__ att, const hf* __restrict__ c2p,
    const hf* __restrict__ F, const float* __restrict__ mask)
{
    int bh = blockIdx.y;
    int warp = threadIdx.x >> 5, lane = threadIdx.x & 31;
    int q = blockIdx.x * 8 + warp;
    int b = bh >> 4;
    size_t rowOff = ((size_t)bh * SS + q) * SS;
    const float scale = 0.07216878364870323f; // 1/sqrt(64*3)

    const __half2* s1r = (const __half2*)(att + rowOff);
    const hf* Fbh = F + (size_t)bh * 2048 * SS;
    const __half2* p2r = (const __half2*)(Fbh + (size_t)(q + 512) * SS);
    const hf* c2r = c2p + ((size_t)bh * SS + q) * PP;
    const float* mk = mask + b * SS;

    int klo = q - 511, khi = q + 512;   // in-band: klo <= k <= khi

    float v[32];
    float mx = -1e30f;
    #pragma unroll
    for (int i = 0; i < 16; i++) {
        int k2 = lane + i * 32;
        int k = k2 * 2;
        float2 s = __half22float2(s1r[k2]);
        float2 p = __half22float2(p2r[k2]);
        if (k < klo)      p.x = __half2float(Fbh[(size_t)(1023 + k) * SS + k]);
        else if (k > khi) p.x = __half2float(Fbh[(size_t)k * SS + k]);
        int k1 = k + 1;
        if (k1 < klo)      p.y = __half2float(Fbh[(size_t)(1023 + k1) * SS + k1]);
        else if (k1 > khi) p.y = __half2float(Fbh[(size_t)k1 * SS + k1]);
        int idx0 = min(max(q - k + SPAN_, 0), PP - 1);
        int idx1 = min(max(q - k1 + SPAN_, 0), PP - 1);
        float c0 = __half2float(c2r[idx0]);
        float c1 = __half2float(c2r[idx1]);
        float v0 = (s.x + c0 + p.x) * scale + (1.f - mk[k])  * -1e9f;
        float v1 = (s.y + c1 + p.y) * scale + (1.f - mk[k1]) * -1e9f;
        v[i*2] = v0; v[i*2+1] = v1;
        mx = fmaxf(mx, fmaxf(v0, v1));
    }
    #pragma unroll
    for (int o = 16; o > 0; o >>= 1) mx = fmaxf(mx, __shfl_xor_sync(0xFFFFFFFFu, mx, o));
    float sum = 0.f;
    #pragma unroll
    for (int i = 0; i < 32; i++) { v[i] = expf(v[i] - mx); sum += v[i]; }
    #pragma unroll
    for (int o = 16; o > 0; o >>= 1) sum += __shfl_xor_sync(0xFFFFFFFFu, sum, o);
    float inv = 1.f / sum;
    __half2* out = (__half2*)(prb + rowOff);
    #pragma unroll
    for (int i = 0; i < 16; i++) {
        int k2 = lane + i * 32;
        out[k2] = __floats2half2_rn(v[i*2] * inv, v[i*2+1] * inv);
    }
}

// ---------------- host --------------------------------------------------------------
extern "C" void kernel_launch(void* const* d_in, const int* in_sizes, int n_in,
                              void* d_out, int out_size)
{
    const int*   ids  = (const int*)d_in[0];
    const int*   segs = (const int*)d_in[1];
    const float* mask = (const float*)d_in[2];
    const float* tok  = (const float*)d_in[3];
    const float* seg  = (const float*)d_in[4];
    const float* elg  = (const float*)d_in[5];
    const float* elb  = (const float*)d_in[6];
    const float* rel  = (const float*)d_in[7];
    const float* Wq = (const float*)d_in[8],  *bq = (const float*)d_in[9];
    const float* Wk = (const float*)d_in[10], *bk = (const float*)d_in[11];
    const float* Wv = (const float*)d_in[12], *bv = (const float*)d_in[13];
    const float* Wo = (const float*)d_in[14], *bo = (const float*)d_in[15];
    const float* l1g = (const float*)d_in[16], *l1b = (const float*)d_in[17];
    const float* W1 = (const float*)d_in[18], *b1 = (const float*)d_in[19];
    const float* W2 = (const float*)d_in[20], *b2 = (const float*)d_in[21];
    const float* l2g = (const float*)d_in[22], *l2b = (const float*)d_in[23];

    float *h, *t2, *qb3, *pb2;
    cudaGetSymbolAddress((void**)&h,   g_h);
    cudaGetSymbolAddress((void**)&t2,  g_t2);
    cudaGetSymbolAddress((void**)&qb3, qkv_bias);
    cudaGetSymbolAddress((void**)&pb2, pos_bias);

    hf *hh,*qkv,*cx,*ff,*rl,*pos;
    hf *wqkv,*wpos,*wo_,*w1_,*w2_;
    hf *vt,*pr,*s1,*c2p,*F;
    cudaGetSymbolAddress((void**)&hh,  hb);
    cudaGetSymbolAddress((void**)&qkv, qkvb);  cudaGetSymbolAddress((void**)&cx, cxb);
    cudaGetSymbolAddress((void**)&ff,  ffb);   cudaGetSymbolAddress((void**)&rl, rlb);
    cudaGetSymbolAddress((void**)&pos, posb);
    cudaGetSymbolAddress((void**)&wqkv, wqkvt); cudaGetSymbolAddress((void**)&wpos, wpost);
    cudaGetSymbolAddress((void**)&wo_, wot);
    cudaGetSymbolAddress((void**)&w1_, w1t);   cudaGetSymbolAddress((void**)&w2_, w2t);
    cudaGetSymbolAddress((void**)&vt, vtb);    cudaGetSymbolAddress((void**)&pr, prb);
    cudaGetSymbolAddress((void**)&s1, s1b);    cudaGetSymbolAddress((void**)&c2p, c2pb);
    cudaGetSymbolAddress((void**)&F, Fb_);

    const int SM128 = 3 * (128*128 + 128*128);   // 98304
    const int SM64  = 3 * (128*128 + 64*128);    // 73728
    cudaFuncSetAttribute(gemm_mma<128,0,0>, cudaFuncAttributeMaxDynamicSharedMemorySize, SM128);
    cudaFuncSetAttribute(gemm_mma<128,1,0>, cudaFuncAttributeMaxDynamicSharedMemorySize, SM128);
    cudaFuncSetAttribute(gemm_mma<128,0,1>, cudaFuncAttributeMaxDynamicSharedMemorySize, SM128);
    cudaFuncSetAttribute(gemm_mma<64,0,0>,  cudaFuncAttributeMaxDynamicSharedMemorySize, SM64);

    embed_ln<<<BS, 256>>>(ids, segs, mask, tok, seg, elg, elb);
    cvt_fp16<<<512, 256>>>(rel, rl, (size_t)PP * DD);

    dim3 tb(32, 8);
    const ll DD2 = (ll)DD * DD;
    const ll S2  = (ll)SS * SS;
    const ll SQ  = (ll)SS * 3 * DD;

    transpose_cvt<<<dim3(32,32,4),  tb>>>(Wq, DD2, wqkv,          3*DD2, DD, DD);
    transpose_cvt<<<dim3(32,32,4),  tb>>>(Wk, DD2, wqkv + DD2,    3*DD2, DD, DD);
    transpose_cvt<<<dim3(32,32,4),  tb>>>(Wv, DD2, wqkv + 2*DD2,  3*DD2, DD, DD);
    transpose_cvt<<<dim3(32,32,4),  tb>>>(Wk, DD2, wpos,          2*DD2, DD, DD);
    transpose_cvt<<<dim3(32,32,4),  tb>>>(Wq, DD2, wpos + DD2,    2*DD2, DD, DD);
    transpose_cvt<<<dim3(32,32,4),  tb>>>(Wo, DD2, wo_,           DD2,   DD, DD);
    transpose_cvt<<<dim3(128,32,4), tb>>>(W1, (ll)DD*FFD, w1_, (ll)FFD*DD, DD, FFD);
    transpose_cvt<<<dim3(32,128,4), tb>>>(W2, (ll)FFD*DD, w2_, (ll)DD*FFD, FFD, DD);
    concat_bias<<<dim3(4,1,4), 256>>>(bq, bk, bv, pb2, qb3);

    for (int l = 0; l < LL; l++) {
        const hf* wqkvL = wqkv + (size_t)l * 3 * DD2;
        const hf* wposL = wpos + (size_t)l * 2 * DD2;
        const hf* woL   = wo_  + (size_t)l * DD2;
        const hf* w1L   = w1_  + (size_t)l * FFD * DD;
        const hf* w2L   = w2_  + (size_t)l * DD * FFD;
        const float* qb3L = qb3 + (size_t)l * 3 * DD;
        const float* pb2L = pb2 + (size_t)l * 2 * DD;
        const float* bo_ = bo + (size_t)l*DD;
        const float* b1_ = b1 + (size_t)l*FFD;
        const float* b2_ = b2 + (size_t)l*DD;
        const float* g1 = l1g + (size_t)l*DD;    const float* be1 = l1b + (size_t)l*DD;
        const float* g2 = l2g + (size_t)l*DD;    const float* be2 = l2b + (size_t)l*DD;

        gemm_mma<128,0,0><<<dim3(24,32,1), 256, SM128>>>(hh,DD,0,0, wqkvL,DD,0,0,
            (float*)0, qkv, 3*DD,0,0, DD, qb3L);
        gemm_mma<128,0,0><<<dim3(16,8,1), 256, SM128>>>(rl,DD,0,0, wposL,DD,0,0,
            (float*)0, pos, 2*DD,0,0, DD, pb2L);

        const hf* q = qkv;
        const hf* k = qkv + DD;
        const hf* v = qkv + 2*DD;
        const hf* pk = pos;
        const hf* pq = pos + DD;

        gemm_mma<128,0,0><<<dim3(8,8,64), 256, SM128>>>(q,3*DD,SQ,64, k,3*DD,SQ,64,
            (float*)0, s1, SS,16*S2,S2, 64, (const float*)0);
        gemm_mma<128,0,0><<<dim3(8,8,64), 256, SM128>>>(q,3*DD,SQ,64, pk,2*DD,0,64,
            (float*)0, c2p, PP,16*S2,S2, 64, (const float*)0);
        // p2c with skewed epilogue: A = k (M-dim), B = posq (N-dim) -> F
        gemm_mma<128,0,1><<<dim3(8,8,64), 256, SM128>>>(k,3*DD,SQ,64, pq,2*DD,0,64,
            (float*)0, F, 0,0,0, 64, (const float*)0);

        softmax_rel<<<dim3(SS/8, 64), 256>>>(s1, c2p, F, mask);
        vt_cvt<<<dim3(32,2,64), tb>>>(v, 3*DD, vt);

        gemm_mma<64,0,0><<<dim3(1,8,64), 256, SM64>>>(pr,SS,16*S2,S2, vt,SS,(ll)16*64*SS,(ll)64*SS,
            (float*)0, cx, DD,(ll)SS*DD,64, SS, (const float*)0);

        gemm_mma<128,0,0><<<dim3(8,32,1), 256, SM128>>>(cx,DD,0,0, woL,DD,0,0,
            t2, (hf*)0, DD,0,0, DD, bo_);
        add_ln<<<BS, 256>>>(h, t2, g1, be1, h);

        gemm_mma<128,1,0><<<dim3(32,32,1), 256, SM128>>>(hh,DD,0,0, w1L,DD,0,0,
            (float*)0, ff, FFD,0,0, DD, b1_);
        gemm_mma<128,0,0><<<dim3(8,32,1), 256, SM128>>>(ff,FFD,0,0, w2L,FFD,0,0,
            t2, (hf*)0, DD,0,0, FFD, b2_);
        add_ln<<<BS, 256>>>(h, t2, g2, be2,
                            (l == LL-1) ? (float*)d_out : h);
    }
}

// round 13
// speedup vs baseline: 1.1702x; 1.1702x over previous
#include <cuda_runtime.h>
#include <cuda_fp16.h>
#include <math.h>
#include <stdint.h>

#define BB 4
#define SS 1024
#define DD 1024
#define HH 16
#define DHH 64
#define FFD 4096
#define LL 4
#define PP 1024
#define SPAN_ 512
#define BS (BB*SS)

typedef long long ll;
typedef __half hf;

// ---------------- scratch ------------------------------------------------------
__device__ float g_h [BS*DD];
__device__ float g_t2[BS*DD];
__device__ float qkv_bias[4*3*DD];
__device__ float pos_bias[4*2*DD];

__device__ hf hb    [BS*DD];
__device__ hf qkvb  [(size_t)BS*3*DD];
__device__ hf cxb   [BS*DD];
__device__ hf ffb   [(size_t)BS*FFD];
__device__ hf rlb   [PP*DD];
__device__ hf posb  [(size_t)PP*2*DD];
__device__ hf wqkvt [(size_t)4*3*DD*DD];
__device__ hf wpost [(size_t)4*2*DD*DD];
__device__ hf wot   [(size_t)4*DD*DD];
__device__ hf w1t   [(size_t)4*FFD*DD];
__device__ hf w2t   [(size_t)4*DD*FFD];
__device__ hf vtb   [(size_t)BB*HH*DHH*SS];
__device__ hf prb   [(size_t)BB*HH*SS*SS];
__device__ hf s1b   [(size_t)BB*HH*SS*SS];
__device__ hf c2pb  [(size_t)BB*HH*SS*PP];
__device__ hf p2cb  [(size_t)BB*HH*SS*PP];

// ---------------- helpers ------------------------------------------------------
__device__ __forceinline__ uint32_t smem_u32(const void* p) {
    uint32_t a;
    asm("{ .reg .u64 t; cvta.to.shared.u64 t, %1; cvt.u32.u64 %0, t; }" : "=r"(a) : "l"(p));
    return a;
}
__device__ __forceinline__ void cpa16(uint32_t dst, const void* src) {
    asm volatile("cp.async.cg.shared.global [%0], [%1], 16;" :: "r"(dst), "l"(src));
}
__device__ __forceinline__ void cpa_commit() { asm volatile("cp.async.commit_group;" ::: "memory"); }

__device__ __forceinline__ void ldm4(uint32_t* r, uint32_t addr) {
    asm volatile("ldmatrix.sync.aligned.m8n8.x4.shared.b16 {%0,%1,%2,%3}, [%4];"
                 : "=r"(r[0]), "=r"(r[1]), "=r"(r[2]), "=r"(r[3]) : "r"(addr));
}
__device__ __forceinline__ void mma16816(float* d, const uint32_t* a, const uint32_t* b) {
    asm volatile("mma.sync.aligned.m16n8k16.row.col.f32.f16.f16.f32 "
                 "{%0,%1,%2,%3}, {%4,%5,%6,%7}, {%8,%9}, {%0,%1,%2,%3};"
                 : "+f"(d[0]), "+f"(d[1]), "+f"(d[2]), "+f"(d[3])
                 : "r"(a[0]), "r"(a[1]), "r"(a[2]), "r"(a[3]), "r"(b[0]), "r"(b[1]));
}

// ---------------- fp16 mma.sync GEMM, 3-stage, 1 sync/chunk (validated) ----------
template <int NT, int ACT>
__global__ void __launch_bounds__(256) gemm_mma(
    const hf* __restrict__ A, int ldA, ll aSB, ll aSH,
    const hf* __restrict__ B, int ldB, ll bSB, ll bSH,
    float* __restrict__ C, hf* __restrict__ Ch,
    int ldC, ll cSB, ll cSH,
    int K, const float* __restrict__ bias)
{
    constexpr int ABY = 128 * 128;
    constexpr int BBY = NT * 128;
    constexpr int STAGE = ABY + BBY;
    constexpr int MT = (NT == 128) ? 4 : 2;
    constexpr int JT = 4;

    extern __shared__ char smem_raw[];
    uint32_t sbase = smem_u32(smem_raw);

    int tid = threadIdx.x, lane = tid & 31, wid = tid >> 5;
    int z = blockIdx.z;

    int warpM, warpN;
    if (NT == 128) { warpM = (wid & 1) * 64; warpN = (wid >> 1) * 32; }
    else           { warpM = (wid & 3) * 32; warpN = (wid >> 2) * 32; }

    const hf* Ab = A + (size_t)((ll)(z >> 4) * aSB + (ll)(z & 15) * aSH)
                     + (size_t)blockIdx.y * 128 * ldA;
    const hf* Bb = B + (size_t)((ll)(z >> 4) * bSB + (ll)(z & 15) * bSH)
                     + (size_t)blockIdx.x * NT * ldB;

    int NC = K >> 6;

    auto load_chunk = [&](int cn, int stage) {
        const hf* Ap = Ab + cn * 64;
        const hf* Bp = Bb + cn * 64;
        uint32_t Ad = sbase + stage * STAGE;
        uint32_t Bd = Ad + ABY;
        #pragma unroll
        for (int i = 0; i < 4; i++) {
            int idx = tid + i * 256;
            int r = idx >> 3, c = idx & 7;
            cpa16(Ad + r * 128 + ((c ^ (r & 7)) << 4), Ap + (size_t)r * ldA + c * 8);
        }
        #pragma unroll
        for (int i = 0; i < NT / 32; i++) {
            int idx = tid + i * 256;
            int r = idx >> 3, c = idx & 7;
            cpa16(Bd + r * 128 + ((c ^ (r & 7)) << 4), Bp + (size_t)r * ldB + c * 8);
        }
        cpa_commit();
    };

    float acc[MT][JT][4];
    #pragma unroll
    for (int i = 0; i < MT; i++)
        #pragma unroll
        for (int j = 0; j < JT; j++)
            #pragma unroll
            for (int e = 0; e < 4; e++) acc[i][j][e] = 0.f;

    load_chunk(0, 0);
    if (NC > 1) load_chunk(1, 1);

    for (int c = 0; c < NC; c++) {
        if (c + 1 < NC) asm volatile("cp.async.wait_group 1;" ::: "memory");
        else            asm volatile("cp.async.wait_group 0;" ::: "memory");
        __syncthreads();

        uint32_t Abuf = sbase + (c % 3) * STAGE;
        uint32_t Bbuf = Abuf + ABY;
        #pragma unroll
        for (int ks = 0; ks < 4; ks++) {
            uint32_t a[MT][4], b[JT][2];
            #pragma unroll
            for (int i = 0; i < MT; i++) {
                int row = warpM + i * 16 + (lane & 15);
                int cc = ks * 2 + (lane >> 4);
                ldm4(a[i], Abuf + row * 128 + (((cc ^ (row & 7)) << 4)));
            }
            #pragma unroll
            for (int j = 0; j < JT / 2; j++) {
                int n = warpN + j * 16 + ((lane >> 4) << 3) + (lane & 7);
                int cc = ks * 2 + ((lane >> 3) & 1);
                uint32_t t[4];
                ldm4(t, Bbuf + n * 128 + (((cc ^ (n & 7)) << 4)));
                b[j*2][0] = t[0];   b[j*2][1] = t[1];
                b[j*2+1][0] = t[2]; b[j*2+1][1] = t[3];
            }
            #pragma unroll
            for (int i = 0; i < MT; i++)
                #pragma unroll
                for (int j = 0; j < JT; j++)
                    mma16816(acc[i][j], a[i], b[j]);
        }
        if (c + 2 < NC) load_chunk(c + 2, (c + 2) % 3);
    }

    ll cO = (ll)(z >> 4) * cSB + (ll)(z & 15) * cSH;
    int m0 = blockIdx.y * 128, n0 = blockIdx.x * NT;
    int quad = lane >> 2, l4 = lane & 3;

    #pragma unroll
    for (int i = 0; i < MT; i++) {
        int r0 = m0 + warpM + i * 16 + quad;
        #pragma unroll
        for (int j = 0; j < JT; j++) {
            int col = n0 + warpN + j * 8 + l4 * 2;
            float b0 = 0.f, b1 = 0.f;
            if (bias) { b0 = bias[col]; b1 = bias[col + 1]; }
            #pragma unroll
            for (int half = 0; half < 2; half++) {
                int row = r0 + half * 8;
                float v0 = acc[i][j][half*2 + 0] + b0;
                float v1 = acc[i][j][half*2 + 1] + b1;
                if (ACT) {
                    v0 = 0.5f * v0 * (1.f + erff(v0 * 0.70710678118654752f));
                    v1 = 0.5f * v1 * (1.f + erff(v1 * 0.70710678118654752f));
                }
                size_t base = (size_t)cO + (size_t)row * ldC + col;
                if (C) *(float2*)(C + base) = make_float2(v0, v1);
                if (Ch) *(__half2*)(Ch + base) =
                    __halves2half2(__float2half(v0), __float2half(v1));
            }
        }
    }
}

// ---------------- converters -----------------------------------------------------
__global__ __launch_bounds__(256) void cvt_fp16(
    const float* __restrict__ in, hf* __restrict__ out, size_t n)
{
    for (size_t i = blockIdx.x * 256ull + threadIdx.x; i < n; i += gridDim.x * 256ull)
        out[i] = __float2half(in[i]);
}

__global__ void concat_bias(const float* bq, const float* bk, const float* bv,
                            float* out2, float* out3)
{
    int l = blockIdx.z;
    const float* a = bq + (size_t)l * DD;
    const float* b = bk + (size_t)l * DD;
    const float* c = bv + (size_t)l * DD;
    float* o3 = out3 + (size_t)l * 3 * DD;
    float* o2 = out2 + (size_t)l * 2 * DD;
    int i = blockIdx.x * 256 + threadIdx.x;
    if (i < DD) {
        o3[i] = a[i]; o3[i + DD] = b[i]; o3[i + 2*DD] = c[i];
        o2[i] = b[i]; o2[i + DD] = a[i];
    }
}

__global__ void transpose_cvt(
    const float* __restrict__ in, ll inLS, hf* __restrict__ out, ll outLS,
    int K, int N)
{
    in  += (size_t)blockIdx.z * inLS;
    out += (size_t)blockIdx.z * outLS;
    __shared__ float t[32][33];
    int k0 = blockIdx.y * 32, n0 = blockIdx.x * 32;
    int tx = threadIdx.x, ty = threadIdx.y;
    for (int i = ty; i < 32; i += 8)
        t[i][tx] = in[(size_t)(k0 + i) * N + n0 + tx];
    __syncthreads();
    for (int i = ty; i < 32; i += 8)
        out[(size_t)(n0 + i) * K + k0 + tx] = __float2half(t[tx][i]);
}

__global__ void vt_cvt(const hf* __restrict__ v, int ldv, hf* __restrict__ out)
{
    __shared__ hf t[32][33];
    int bh = blockIdx.z, b = bh >> 4, h = bh & 15;
    int s0 = blockIdx.x * 32, d0 = blockIdx.y * 32;
    int tx = threadIdx.x, ty = threadIdx.y;
    for (int i = ty; i < 32; i += 8)
        t[i][tx] = v[((size_t)b * SS + s0 + i) * ldv + h * 64 + d0 + tx];
    __syncthreads();
    for (int i = ty; i < 32; i += 8)
        out[((size_t)bh * 64 + d0 + i) * SS + s0 + tx] = t[tx][i];
}

// ---------------- embedding / LN ----------------------------------------------
__global__ __launch_bounds__(256) void embed_ln(
    const int* __restrict__ ids, const int* __restrict__ segs,
    const float* __restrict__ mask, const float* __restrict__ tok,
    const float* __restrict__ seg, const float* __restrict__ g,
    const float* __restrict__ b)
{
    int row = blockIdx.x, tid = threadIdx.x;
    const float* t  = tok + (size_t)ids[row]  * DD;
    const float* sg = seg + (size_t)segs[row] * DD;
    float x[4]; float s = 0.f;
    #pragma unroll
    for (int i = 0; i < 4; i++) { int c = tid + i*256; x[i] = t[c] + sg[c]; s += x[i]; }
    __shared__ float red[256];
    red[tid] = s; __syncthreads();
    for (int o = 128; o > 0; o >>= 1) { if (tid < o) red[tid] += red[tid+o]; __syncthreads(); }
    float m = red[0] * (1.f / DD); __syncthreads();
    s = 0.f;
    #pragma unroll
    for (int i = 0; i < 4; i++) { float d = x[i] - m; s += d*d; }
    red[tid] = s; __syncthreads();
    for (int o = 128; o > 0; o >>= 1) { if (tid < o) red[tid] += red[tid+o]; __syncthreads(); }
    float inv = rsqrtf(red[0] * (1.f / DD) + 1e-12f);
    float mk = mask[row];
    #pragma unroll
    for (int i = 0; i < 4; i++) {
        int c = tid + i*256;
        float y = ((x[i] - m) * inv * g[c] + b[c]) * mk;
        size_t o = (size_t)row * DD + c;
        g_h[o] = y; hb[o] = __float2half(y);
    }
}

__global__ __launch_bounds__(256) void add_ln(
    const float* __restrict__ base, const float* __restrict__ addv,
    const float* __restrict__ g, const float* __restrict__ b,
    float* __restrict__ out)
{
    int row = blockIdx.x, tid = threadIdx.x;
    size_t off = (size_t)row * DD;
    float x[4]; float s = 0.f;
    #pragma unroll
    for (int i = 0; i < 4; i++) { int c = tid + i*256; x[i] = base[off+c] + addv[off+c]; s += x[i]; }
    __shared__ float red[256];
    red[tid] = s; __syncthreads();
    for (int o = 128; o > 0; o >>= 1) { if (tid < o) red[tid] += red[tid+o]; __syncthreads(); }
    float m = red[0] * (1.f / DD); __syncthreads();
    s = 0.f;
    #pragma unroll
    for (int i = 0; i < 4; i++) { float d = x[i] - m; s += d*d; }
    red[tid] = s; __syncthreads();
    for (int o = 128; o > 0; o >>= 1) { if (tid < o) red[tid] += red[tid+o]; __syncthreads(); }
    float inv = rsqrtf(red[0] * (1.f / DD) + 1e-12f);
    #pragma unroll
    for (int i = 0; i < 4; i++) {
        int c = tid + i*256;
        float y = (x[i] - m) * inv * g[c] + b[c];
        out[off + c] = y; hb[off + c] = __float2half(y);
    }
}

// ---------------- warp-per-row softmax, direct p2c gather -----------------------
// block = 256 (8 warps = 8 rows); grid (SS/8, BB*HH)
__global__ __launch_bounds__(256) void softmax_rel(
    const hf* __restrict__ att, const hf* __restrict__ c2p,
    const hf* __restrict__ p2c, const float* __restrict__ mask)
{
    int bh = blockIdx.y;
    int warp = threadIdx.x >> 5, lane = threadIdx.x & 31;
    int q = blockIdx.x * 8 + warp;
    int b = bh >> 4;
    size_t rowOff = ((size_t)bh * SS + q) * SS;
    const float scale = 0.07216878364870323f; // 1/sqrt(64*3)

    const __half2* s1r = (const __half2*)(att + rowOff);
    const hf* c2r  = c2p + ((size_t)bh * SS + q) * PP;
    const hf* p2bh = p2c + (size_t)bh * SS * PP;
    const float* mk = mask + b * SS;

    float v[32];
    float mx = -1e30f;
    #pragma unroll
    for (int i = 0; i < 16; i++) {
        int k2 = lane + i * 32;
        int k = k2 * 2, k1 = k + 1;
        float2 s = __half22float2(s1r[k2]);
        int idx0 = min(max(q - k  + SPAN_, 0), PP - 1);
        int idx1 = min(max(q - k1 + SPAN_, 0), PP - 1);
        float c0 = __half2float(c2r[idx0]);
        float c1 = __half2float(c2r[idx1]);
        float p0 = __half2float(p2bh[(size_t)k  * PP + idx0]);
        float p1 = __half2float(p2bh[(size_t)k1 * PP + idx1]);
        float v0 = (s.x + c0 + p0) * scale + (1.f - mk[k])  * -1e9f;
        float v1 = (s.y + c1 + p1) * scale + (1.f - mk[k1]) * -1e9f;
        v[i*2] = v0; v[i*2+1] = v1;
        mx = fmaxf(mx, fmaxf(v0, v1));
    }
    #pragma unroll
    for (int o = 16; o > 0; o >>= 1) mx = fmaxf(mx, __shfl_xor_sync(0xFFFFFFFFu, mx, o));
    float sum = 0.f;
    #pragma unroll
    for (int i = 0; i < 32; i++) { v[i] = expf(v[i] - mx); sum += v[i]; }
    #pragma unroll
    for (int o = 16; o > 0; o >>= 1) sum += __shfl_xor_sync(0xFFFFFFFFu, sum, o);
    float inv = 1.f / sum;
    __half2* out = (__half2*)(prb + rowOff);
    #pragma unroll
    for (int i = 0; i < 16; i++) {
        int k2 = lane + i * 32;
        out[k2] = __floats2half2_rn(v[i*2] * inv, v[i*2+1] * inv);
    }
}

// ---------------- host --------------------------------------------------------------
extern "C" void kernel_launch(void* const* d_in, const int* in_sizes, int n_in,
                              void* d_out, int out_size)
{
    const int*   ids  = (const int*)d_in[0];
    const int*   segs = (const int*)d_in[1];
    const float* mask = (const float*)d_in[2];
    const float* tok  = (const float*)d_in[3];
    const float* seg  = (const float*)d_in[4];
    const float* elg  = (const float*)d_in[5];
    const float* elb  = (const float*)d_in[6];
    const float* rel  = (const float*)d_in[7];
    const float* Wq = (const float*)d_in[8],  *bq = (const float*)d_in[9];
    const float* Wk = (const float*)d_in[10], *bk = (const float*)d_in[11];
    const float* Wv = (const float*)d_in[12], *bv = (const float*)d_in[13];
    const float* Wo = (const float*)d_in[14], *bo = (const float*)d_in[15];
    const float* l1g = (const float*)d_in[16], *l1b = (const float*)d_in[17];
    const float* W1 = (const float*)d_in[18], *b1 = (const float*)d_in[19];
    const float* W2 = (const float*)d_in[20], *b2 = (const float*)d_in[21];
    const float* l2g = (const float*)d_in[22], *l2b = (const float*)d_in[23];

    float *h, *t2, *qb3, *pb2;
    cudaGetSymbolAddress((void**)&h,   g_h);
    cudaGetSymbolAddress((void**)&t2,  g_t2);
    cudaGetSymbolAddress((void**)&qb3, qkv_bias);
    cudaGetSymbolAddress((void**)&pb2, pos_bias);

    hf *hh,*qkv,*cx,*ff,*rl,*pos;
    hf *wqkv,*wpos,*wo_,*w1_,*w2_;
    hf *vt,*pr,*s1,*c2p,*p2c;
    cudaGetSymbolAddress((void**)&hh,  hb);
    cudaGetSymbolAddress((void**)&qkv, qkvb);  cudaGetSymbolAddress((void**)&cx, cxb);
    cudaGetSymbolAddress((void**)&ff,  ffb);   cudaGetSymbolAddress((void**)&rl, rlb);
    cudaGetSymbolAddress((void**)&pos, posb);
    cudaGetSymbolAddress((void**)&wqkv, wqkvt); cudaGetSymbolAddress((void**)&wpos, wpost);
    cudaGetSymbolAddress((void**)&wo_, wot);
    cudaGetSymbolAddress((void**)&w1_, w1t);   cudaGetSymbolAddress((void**)&w2_, w2t);
    cudaGetSymbolAddress((void**)&vt, vtb);    cudaGetSymbolAddress((void**)&pr, prb);
    cudaGetSymbolAddress((void**)&s1, s1b);    cudaGetSymbolAddress((void**)&c2p, c2pb);
    cudaGetSymbolAddress((void**)&p2c, p2cb);

    const int SM128 = 3 * (128*128 + 128*128);   // 98304
    const int SM64  = 3 * (128*128 + 64*128);    // 73728
    cudaFuncSetAttribute(gemm_mma<128,0>, cudaFuncAttributeMaxDynamicSharedMemorySize, SM128);
    cudaFuncSetAttribute(gemm_mma<128,1>, cudaFuncAttributeMaxDynamicSharedMemorySize, SM128);
    cudaFuncSetAttribute(gemm_mma<64,0>,  cudaFuncAttributeMaxDynamicSharedMemorySize, SM64);

    embed_ln<<<BS, 256>>>(ids, segs, mask, tok, seg, elg, elb);
    cvt_fp16<<<512, 256>>>(rel, rl, (size_t)PP * DD);

    dim3 tb(32, 8);
    const ll DD2 = (ll)DD * DD;
    const ll S2  = (ll)SS * SS;
    const ll SQ  = (ll)SS * 3 * DD;

    transpose_cvt<<<dim3(32,32,4),  tb>>>(Wq, DD2, wqkv,          3*DD2, DD, DD);
    transpose_cvt<<<dim3(32,32,4),  tb>>>(Wk, DD2, wqkv + DD2,    3*DD2, DD, DD);
    transpose_cvt<<<dim3(32,32,4),  tb>>>(Wv, DD2, wqkv + 2*DD2,  3*DD2, DD, DD);
    transpose_cvt<<<dim3(32,32,4),  tb>>>(Wk, DD2, wpos,          2*DD2, DD, DD);
    transpose_cvt<<<dim3(32,32,4),  tb>>>(Wq, DD2, wpos + DD2,    2*DD2, DD, DD);
    transpose_cvt<<<dim3(32,32,4),  tb>>>(Wo, DD2, wo_,           DD2,   DD, DD);
    transpose_cvt<<<dim3(128,32,4), tb>>>(W1, (ll)DD*FFD, w1_, (ll)FFD*DD, DD, FFD);
    transpose_cvt<<<dim3(32,128,4), tb>>>(W2, (ll)FFD*DD, w2_, (ll)DD*FFD, FFD, DD);
    concat_bias<<<dim3(4,1,4), 256>>>(bq, bk, bv, pb2, qb3);

    for (int l = 0; l < LL; l++) {
        const hf* wqkvL = wqkv + (size_t)l * 3 * DD2;
        const hf* wposL = wpos + (size_t)l * 2 * DD2;
        const hf* woL   = wo_  + (size_t)l * DD2;
        const hf* w1L   = w1_  + (size_t)l * FFD * DD;
        const hf* w2L   = w2_  + (size_t)l * DD * FFD;
        const float* qb3L = qb3 + (size_t)l * 3 * DD;
        const float* pb2L = pb2 + (size_t)l * 2 * DD;
        const float* bo_ = bo + (size_t)l*DD;
        const float* b1_ = b1 + (size_t)l*FFD;
        const float* b2_ = b2 + (size_t)l*DD;
        const float* g1 = l1g + (size_t)l*DD;    const float* be1 = l1b + (size_t)l*DD;
        const float* g2 = l2g + (size_t)l*DD;    const float* be2 = l2b + (size_t)l*DD;

        gemm_mma<128,0><<<dim3(24,32,1), 256, SM128>>>(hh,DD,0,0, wqkvL,DD,0,0,
            (float*)0, qkv, 3*DD,0,0, DD, qb3L);
        gemm_mma<128,0><<<dim3(16,8,1), 256, SM128>>>(rl,DD,0,0, wposL,DD,0,0,
            (float*)0, pos, 2*DD,0,0, DD, pb2L);

        const hf* q = qkv;
        const hf* k = qkv + DD;
        const hf* v = qkv + 2*DD;
        const hf* pk = pos;
        const hf* pq = pos + DD;

        gemm_mma<128,0><<<dim3(8,8,64), 256, SM128>>>(q,3*DD,SQ,64, k,3*DD,SQ,64,
            (float*)0, s1, SS,16*S2,S2, 64, (const float*)0);
        gemm_mma<128,0><<<dim3(8,8,64), 256, SM128>>>(q,3*DD,SQ,64, pk,2*DD,0,64,
            (float*)0, c2p, PP,16*S2,S2, 64, (const float*)0);
        gemm_mma<128,0><<<dim3(8,8,64), 256, SM128>>>(k,3*DD,SQ,64, pq,2*DD,0,64,
            (float*)0, p2c, PP,16*S2,S2, 64, (const float*)0);

        softmax_rel<<<dim3(SS/8, 64), 256>>>(s1, c2p, p2c, mask);
        vt_cvt<<<dim3(32,2,64), tb>>>(v, 3*DD, vt);

        gemm_mma<64,0><<<dim3(1,8,64), 256, SM64>>>(pr,SS,16*S2,S2, vt,SS,(ll)16*64*SS,(ll)64*SS,
            (float*)0, cx, DD,(ll)SS*DD,64, SS, (const float*)0);

        gemm_mma<128,0><<<dim3(8,32,1), 256, SM128>>>(cx,DD,0,0, woL,DD,0,0,
            t2, (hf*)0, DD,0,0, DD, bo_);
        add_ln<<<BS, 256>>>(h, t2, g1, be1, h);

        gemm_mma<128,1><<<dim3(32,32,1), 256, SM128>>>(hh,DD,0,0, w1L,DD,0,0,
            (float*)0, ff, FFD,0,0, DD, b1_);
        gemm_mma<128,0><<<dim3(8,32,1), 256, SM128>>>(ff,FFD,0,0, w2L,FFD,0,0,
            t2, (hf*)0, DD,0,0, FFD, b2_);
        add_ln<<<BS, 256>>>(h, t2, g2, be2,
                            (l == LL-1) ? (float*)d_out : h);
    }
}

// round 14
// speedup vs baseline: 1.1895x; 1.0165x over previous
#include <cuda_runtime.h>
#include <cuda_fp16.h>
#include <math.h>
#include <stdint.h>

#define BB 4
#define SS 1024
#define DD 1024
#define HH 16
#define DHH 64
#define FFD 4096
#define LL 4
#define PP 1024
#define SPAN_ 512
#define BS (BB*SS)

typedef long long ll;
typedef __half hf;

// ---------------- scratch ------------------------------------------------------
__device__ float g_h [BS*DD];
__device__ float g_t2[BS*DD];
__device__ float qkv_bias[4*3*DD];
__device__ float pos_bias[4*2*DD];

__device__ hf hb    [BS*DD];
__device__ hf qkvb  [(size_t)BS*3*DD];
__device__ hf cxb   [BS*DD];
__device__ hf ffb   [(size_t)BS*FFD];
__device__ hf rlb   [PP*DD];
__device__ hf posb  [(size_t)PP*2*DD];
__device__ hf wqkvt [(size_t)4*3*DD*DD];
__device__ hf wpost [(size_t)4*2*DD*DD];
__device__ hf wot   [(size_t)4*DD*DD];
__device__ hf w1t   [(size_t)4*FFD*DD];
__device__ hf w2t   [(size_t)4*DD*FFD];
__device__ hf vtb   [(size_t)BB*HH*DHH*SS];
__device__ hf c2pb  [(size_t)BB*HH*SS*PP];
__device__ hf p2cb  [(size_t)BB*HH*SS*PP];

// ---------------- helpers ------------------------------------------------------
__device__ __forceinline__ uint32_t smem_u32(const void* p) {
    uint32_t a;
    asm("{ .reg .u64 t; cvta.to.shared.u64 t, %1; cvt.u32.u64 %0, t; }" : "=r"(a) : "l"(p));
    return a;
}
__device__ __forceinline__ void cpa16(uint32_t dst, const void* src) {
    asm volatile("cp.async.cg.shared.global [%0], [%1], 16;" :: "r"(dst), "l"(src));
}
__device__ __forceinline__ void cpa_commit() { asm volatile("cp.async.commit_group;" ::: "memory"); }

__device__ __forceinline__ void ldm4(uint32_t* r, uint32_t addr) {
    asm volatile("ldmatrix.sync.aligned.m8n8.x4.shared.b16 {%0,%1,%2,%3}, [%4];"
                 : "=r"(r[0]), "=r"(r[1]), "=r"(r[2]), "=r"(r[3]) : "r"(addr));
}
__device__ __forceinline__ void mma16816(float* d, const uint32_t* a, const uint32_t* b) {
    asm volatile("mma.sync.aligned.m16n8k16.row.col.f32.f16.f16.f32 "
                 "{%0,%1,%2,%3}, {%4,%5,%6,%7}, {%8,%9}, {%0,%1,%2,%3};"
                 : "+f"(d[0]), "+f"(d[1]), "+f"(d[2]), "+f"(d[3])
                 : "r"(a[0]), "r"(a[1]), "r"(a[2]), "r"(a[3]), "r"(b[0]), "r"(b[1]));
}

// ---------------- fp16 mma.sync GEMM, 3-stage, 1 sync/chunk (validated) ----------
template <int NT, int ACT>
__global__ void __launch_bounds__(256) gemm_mma(
    const hf* __restrict__ A, int ldA, ll aSB, ll aSH,
    const hf* __restrict__ B, int ldB, ll bSB, ll bSH,
    float* __restrict__ C, hf* __restrict__ Ch,
    int ldC, ll cSB, ll cSH,
    int K, const float* __restrict__ bias)
{
    constexpr int ABY = 128 * 128;
    constexpr int BBY = NT * 128;
    constexpr int STAGE = ABY + BBY;
    constexpr int MT = (NT == 128) ? 4 : 2;
    constexpr int JT = 4;

    extern __shared__ char smem_raw[];
    uint32_t sbase = smem_u32(smem_raw);

    int tid = threadIdx.x, lane = tid & 31, wid = tid >> 5;
    int z = blockIdx.z;

    int warpM, warpN;
    if (NT == 128) { warpM = (wid & 1) * 64; warpN = (wid >> 1) * 32; }
    else           { warpM = (wid & 3) * 32; warpN = (wid >> 2) * 32; }

    const hf* Ab = A + (size_t)((ll)(z >> 4) * aSB + (ll)(z & 15) * aSH)
                     + (size_t)blockIdx.y * 128 * ldA;
    const hf* Bb = B + (size_t)((ll)(z >> 4) * bSB + (ll)(z & 15) * bSH)
                     + (size_t)blockIdx.x * NT * ldB;

    int NC = K >> 6;

    auto load_chunk = [&](int cn, int stage) {
        const hf* Ap = Ab + cn * 64;
        const hf* Bp = Bb + cn * 64;
        uint32_t Ad = sbase + stage * STAGE;
        uint32_t Bd = Ad + ABY;
        #pragma unroll
        for (int i = 0; i < 4; i++) {
            int idx = tid + i * 256;
            int r = idx >> 3, c = idx & 7;
            cpa16(Ad + r * 128 + ((c ^ (r & 7)) << 4), Ap + (size_t)r * ldA + c * 8);
        }
        #pragma unroll
        for (int i = 0; i < NT / 32; i++) {
            int idx = tid + i * 256;
            int r = idx >> 3, c = idx & 7;
            cpa16(Bd + r * 128 + ((c ^ (r & 7)) << 4), Bp + (size_t)r * ldB + c * 8);
        }
        cpa_commit();
    };

    float acc[MT][JT][4];
    #pragma unroll
    for (int i = 0; i < MT; i++)
        #pragma unroll
        for (int j = 0; j < JT; j++)
            #pragma unroll
            for (int e = 0; e < 4; e++) acc[i][j][e] = 0.f;

    load_chunk(0, 0);
    if (NC > 1) load_chunk(1, 1);

    for (int c = 0; c < NC; c++) {
        if (c + 1 < NC) asm volatile("cp.async.wait_group 1;" ::: "memory");
        else            asm volatile("cp.async.wait_group 0;" ::: "memory");
        __syncthreads();

        uint32_t Abuf = sbase + (c % 3) * STAGE;
        uint32_t Bbuf = Abuf + ABY;
        #pragma unroll
        for (int ks = 0; ks < 4; ks++) {
            uint32_t a[MT][4], b[JT][2];
            #pragma unroll
            for (int i = 0; i < MT; i++) {
                int row = warpM + i * 16 + (lane & 15);
                int cc = ks * 2 + (lane >> 4);
                ldm4(a[i], Abuf + row * 128 + (((cc ^ (row & 7)) << 4)));
            }
            #pragma unroll
            for (int j = 0; j < JT / 2; j++) {
                int n = warpN + j * 16 + ((lane >> 4) << 3) + (lane & 7);
                int cc = ks * 2 + ((lane >> 3) & 1);
                uint32_t t[4];
                ldm4(t, Bbuf + n * 128 + (((cc ^ (n & 7)) << 4)));
                b[j*2][0] = t[0];   b[j*2][1] = t[1];
                b[j*2+1][0] = t[2]; b[j*2+1][1] = t[3];
            }
            #pragma unroll
            for (int i = 0; i < MT; i++)
                #pragma unroll
                for (int j = 0; j < JT; j++)
                    mma16816(acc[i][j], a[i], b[j]);
        }
        if (c + 2 < NC) load_chunk(c + 2, (c + 2) % 3);
    }

    ll cO = (ll)(z >> 4) * cSB + (ll)(z & 15) * cSH;
    int m0 = blockIdx.y * 128, n0 = blockIdx.x * NT;
    int quad = lane >> 2, l4 = lane & 3;

    #pragma unroll
    for (int i = 0; i < MT; i++) {
        int r0 = m0 + warpM + i * 16 + quad;
        #pragma unroll
        for (int j = 0; j < JT; j++) {
            int col = n0 + warpN + j * 8 + l4 * 2;
            float b0 = 0.f, b1 = 0.f;
            if (bias) { b0 = bias[col]; b1 = bias[col + 1]; }
            #pragma unroll
            for (int half = 0; half < 2; half++) {
                int row = r0 + half * 8;
                float v0 = acc[i][j][half*2 + 0] + b0;
                float v1 = acc[i][j][half*2 + 1] + b1;
                if (ACT) {
                    v0 = 0.5f * v0 * (1.f + erff(v0 * 0.70710678118654752f));
                    v1 = 0.5f * v1 * (1.f + erff(v1 * 0.70710678118654752f));
                }
                size_t base = (size_t)cO + (size_t)row * ldC + col;
                if (C) *(float2*)(C + base) = make_float2(v0, v1);
                if (Ch) *(__half2*)(Ch + base) =
                    __halves2half2(__float2half(v0), __float2half(v1));
            }
        }
    }
}

// ---------------- fused attention: softmax(qk^T + bias) @ V ---------------------
// grid (8 q-tiles, 64 bh), block 256. Warp w owns S-rows w*16..w*16+15.
// SMEM: q[128x64]@0, k2buf@16384(+8192), v2buf@32768(+8192), P[128x64]@49152,
//       factor[128]f@65536, linv[128]f@66048.
__global__ void __launch_bounds__(256) fused_attn(
    const hf* __restrict__ qkv, const hf* __restrict__ vt,
    const hf* __restrict__ c2p, const hf* __restrict__ p2c,
    const float* __restrict__ mask, hf* __restrict__ ctx)
{
    extern __shared__ char smem_raw[];
    uint32_t sbase = smem_u32(smem_raw);
    float* factorArr = (float*)(smem_raw + 65536);
    float* linvArr   = (float*)(smem_raw + 66048);

    int tid = threadIdx.x, lane = tid & 31, wid = tid >> 5;
    int quad = lane >> 2, l4 = lane & 3;
    int q0 = blockIdx.x * 128, bh = blockIdx.y;
    int b = bh >> 4, h = bh & 15;
    const float scale = 0.07216878364870323f; // 1/sqrt(64*3)

    const hf* qsrc = qkv + (size_t)(b*SS + q0) * (3*DD) + h*64;
    const hf* ksrc = qkv + (size_t)(b*SS) * (3*DD) + DD + h*64;
    const hf* vsrc = vt  + (size_t)bh * 64 * SS;
    const hf* c2bh = c2p + (size_t)bh * SS * PP;
    const hf* p2bh = p2c + (size_t)bh * SS * PP;
    const float* mk = mask + b * SS;

    // load q tile + k tile 0 (one commit group)
    for (int i = tid; i < 1024; i += 256) {
        int r = i >> 3, c = i & 7;
        cpa16(sbase + r*128 + ((c^(r&7))<<4), qsrc + (size_t)r*(3*DD) + c*8);
    }
    for (int i = tid; i < 512; i += 256) {
        int r = i >> 3, c = i & 7;
        cpa16(sbase + 16384 + r*128 + ((c^(r&7))<<4), ksrc + (size_t)r*(3*DD) + c*8);
    }
    cpa_commit();

    float accO[2][4][4];
    #pragma unroll
    for (int i = 0; i < 2; i++)
        #pragma unroll
        for (int j = 0; j < 4; j++)
            #pragma unroll
            for (int e = 0; e < 4; e++) accO[i][j][e] = 0.f;
    float mreg[2] = {-1e30f, -1e30f};
    float lreg[2] = {0.f, 0.f};

    int r0 = wid * 16 + quad;

    for (int t = 0; t < 16; t++) {
        asm volatile("cp.async.wait_group 0;" ::: "memory");
        __syncthreads();
        int k0 = t * 64;

        // prefetch V^T tile for this k0
        uint32_t Vb = sbase + 32768 + (t & 1) * 8192;
        for (int i = tid; i < 512; i += 256) {
            int r = i >> 3, c = i & 7;
            cpa16(Vb + r*128 + ((c^(r&7))<<4), vsrc + (size_t)r*SS + k0 + c*8);
        }
        cpa_commit();

        // ---- S = q @ k^T (128 x 64, K = 64) ----
        uint32_t Kb = sbase + 16384 + (t & 1) * 8192;
        float sacc[8][4];
        #pragma unroll
        for (int j = 0; j < 8; j++)
            #pragma unroll
            for (int e = 0; e < 4; e++) sacc[j][e] = 0.f;
        #pragma unroll
        for (int ks = 0; ks < 4; ks++) {
            uint32_t a[4], bb[8][2];
            int row = wid * 16 + (lane & 15);
            int cc = ks * 2 + (lane >> 4);
            ldm4(a, sbase + row*128 + ((cc^(row&7))<<4));
            #pragma unroll
            for (int j = 0; j < 4; j++) {
                int n = j * 16 + ((lane >> 4) << 3) + (lane & 7);
                int c2 = ks * 2 + ((lane >> 3) & 1);
                uint32_t t4[4];
                ldm4(t4, Kb + n*128 + ((c2^(n&7))<<4));
                bb[j*2][0] = t4[0];   bb[j*2][1] = t4[1];
                bb[j*2+1][0] = t4[2]; bb[j*2+1][1] = t4[3];
            }
            #pragma unroll
            for (int j = 0; j < 8; j++) mma16816(sacc[j], a, bb[j]);
        }

        // prefetch next k tile
        if (t + 1 < 16) {
            uint32_t Kn = sbase + 16384 + ((t + 1) & 1) * 8192;
            for (int i = tid; i < 512; i += 256) {
                int r = i >> 3, c = i & 7;
                cpa16(Kn + r*128 + ((c^(r&7))<<4),
                      ksrc + (size_t)(k0 + 64 + r)*(3*DD) + c*8);
            }
            cpa_commit();
        }

        // ---- online softmax over this 64-col tile (rows warp-owned) ----
        #pragma unroll
        for (int half = 0; half < 2; half++) {
            int row = r0 + half * 8;
            int qg = q0 + row;
            const hf* c2r = c2bh + (size_t)qg * PP;
            float v[16];
            float tmax = -1e30f;
            #pragma unroll
            for (int j = 0; j < 8; j++) {
                #pragma unroll
                for (int e = 0; e < 2; e++) {
                    int col = k0 + j*8 + l4*2 + e;
                    int idx = min(max(qg - col + SPAN_, 0), PP - 1);
                    float s = sacc[j][half*2 + e]
                            + __half2float(c2r[idx])
                            + __half2float(p2bh[(size_t)col * PP + idx]);
                    float vv = s * scale + (1.f - mk[col]) * -1e9f;
                    v[j*2 + e] = vv;
                    tmax = fmaxf(tmax, vv);
                }
            }
            tmax = fmaxf(tmax, __shfl_xor_sync(0xFFFFFFFFu, tmax, 1));
            tmax = fmaxf(tmax, __shfl_xor_sync(0xFFFFFFFFu, tmax, 2));
            float mnew = fmaxf(mreg[half], tmax);
            float fac = __expf(mreg[half] - mnew);
            mreg[half] = mnew;
            float sum = 0.f;
            #pragma unroll
            for (int j = 0; j < 8; j++) {
                float p0 = __expf(v[j*2]     - mnew);
                float p1 = __expf(v[j*2 + 1] - mnew);
                sum += p0 + p1;
                int col0 = j*8 + l4*2;
                int u = col0 >> 3;
                uint32_t addr = sbase + 49152 + row*128
                              + ((u ^ (row & 7)) << 4) + (col0 & 7) * 2;
                *(__half2*)(smem_raw + (addr - sbase)) =
                    __halves2half2(__float2half(p0), __float2half(p1));
            }
            sum += __shfl_xor_sync(0xFFFFFFFFu, sum, 1);
            sum += __shfl_xor_sync(0xFFFFFFFFu, sum, 2);
            lreg[half] = lreg[half] * fac + sum;
            if (l4 == 0) factorArr[row] = fac;
        }

        // wait V^T; make P + factors visible
        if (t + 1 < 16) asm volatile("cp.async.wait_group 1;" ::: "memory");
        else            asm volatile("cp.async.wait_group 0;" ::: "memory");
        __syncthreads();

        // ---- O = O*fac + P @ V^T  (128 x 64, K = 64) ----
        int oM = (wid & 3) * 32, oN = (wid >> 2) * 32;
        #pragma unroll
        for (int i = 0; i < 2; i++) {
            #pragma unroll
            for (int half = 0; half < 2; half++) {
                float f = factorArr[oM + i*16 + quad + half*8];
                #pragma unroll
                for (int j = 0; j < 4; j++) {
                    accO[i][j][half*2 + 0] *= f;
                    accO[i][j][half*2 + 1] *= f;
                }
            }
        }
        #pragma unroll
        for (int ks = 0; ks < 4; ks++) {
            uint32_t a[2][4], bb[4][2];
            #pragma unroll
            for (int i = 0; i < 2; i++) {
                int row = oM + i*16 + (lane & 15);
                int cc = ks * 2 + (lane >> 4);
                ldm4(a[i], sbase + 49152 + row*128 + ((cc^(row&7))<<4));
            }
            #pragma unroll
            for (int j = 0; j < 2; j++) {
                int n = oN + j*16 + ((lane >> 4) << 3) + (lane & 7);
                int c2 = ks * 2 + ((lane >> 3) & 1);
                uint32_t t4[4];
                ldm4(t4, Vb + n*128 + ((c2^(n&7))<<4));
                bb[j*2][0] = t4[0];   bb[j*2][1] = t4[1];
                bb[j*2+1][0] = t4[2]; bb[j*2+1][1] = t4[3];
            }
            #pragma unroll
            for (int i = 0; i < 2; i++)
                #pragma unroll
                for (int j = 0; j < 4; j++)
                    mma16816(accO[i][j], a[i], bb[j]);
        }
    }

    if (l4 == 0) {
        linvArr[r0]     = 1.f / lreg[0];
        linvArr[r0 + 8] = 1.f / lreg[1];
    }
    __syncthreads();

    int oM = (wid & 3) * 32, oN = (wid >> 2) * 32;
    #pragma unroll
    for (int i = 0; i < 2; i++) {
        #pragma unroll
        for (int half = 0; half < 2; half++) {
            int row = oM + i*16 + quad + half*8;
            float inv = linvArr[row];
            size_t base = ((size_t)(b*SS + q0 + row)) * DD + h*64 + oN;
            #pragma unroll
            for (int j = 0; j < 4; j++) {
                float v0 = accO[i][j][half*2 + 0] * inv;
                float v1 = accO[i][j][half*2 + 1] * inv;
                *(__half2*)(ctx + base + j*8 + l4*2) =
                    __halves2half2(__float2half(v0), __float2half(v1));
            }
        }
    }
}

// ---------------- converters -----------------------------------------------------
__global__ __launch_bounds__(256) void cvt_fp16(
    const float* __restrict__ in, hf* __restrict__ out, size_t n)
{
    for (size_t i = blockIdx.x * 256ull + threadIdx.x; i < n; i += gridDim.x * 256ull)
        out[i] = __float2half(in[i]);
}

__global__ void concat_bias(const float* bq, const float* bk, const float* bv,
                            float* out2, float* out3)
{
    int l = blockIdx.z;
    const float* a = bq + (size_t)l * DD;
    const float* b = bk + (size_t)l * DD;
    const float* c = bv + (size_t)l * DD;
    float* o3 = out3 + (size_t)l * 3 * DD;
    float* o2 = out2 + (size_t)l * 2 * DD;
    int i = blockIdx.x * 256 + threadIdx.x;
    if (i < DD) {
        o3[i] = a[i]; o3[i + DD] = b[i]; o3[i + 2*DD] = c[i];
        o2[i] = b[i]; o2[i + DD] = a[i];
    }
}

__global__ void transpose_cvt(
    const float* __restrict__ in, ll inLS, hf* __restrict__ out, ll outLS,
    int K, int N)
{
    in  += (size_t)blockIdx.z * inLS;
    out += (size_t)blockIdx.z * outLS;
    __shared__ float t[32][33];
    int k0 = blockIdx.y * 32, n0 = blockIdx.x * 32;
    int tx = threadIdx.x, ty = threadIdx.y;
    for (int i = ty; i < 32; i += 8)
        t[i][tx] = in[(size_t)(k0 + i) * N + n0 + tx];
    __syncthreads();
    for (int i = ty; i < 32; i += 8)
        out[(size_t)(n0 + i) * K + k0 + tx] = __float2half(t[tx][i]);
}

__global__ void vt_cvt(const hf* __restrict__ v, int ldv, hf* __restrict__ out)
{
    __shared__ hf t[32][33];
    int bh = blockIdx.z, b = bh >> 4, h = bh & 15;
    int s0 = blockIdx.x * 32, d0 = blockIdx.y * 32;
    int tx = threadIdx.x, ty = threadIdx.y;
    for (int i = ty; i < 32; i += 8)
        t[i][tx] = v[((size_t)b * SS + s0 + i) * ldv + h * 64 + d0 + tx];
    __syncthreads();
    for (int i = ty; i < 32; i += 8)
        out[((size_t)bh * 64 + d0 + i) * SS + s0 + tx] = t[tx][i];
}

// ---------------- embedding / LN ----------------------------------------------
__global__ __launch_bounds__(256) void embed_ln(
    const int* __restrict__ ids, const int* __restrict__ segs,
    const float* __restrict__ mask, const float* __restrict__ tok,
    const float* __restrict__ seg, const float* __restrict__ g,
    const float* __restrict__ b)
{
    int row = blockIdx.x, tid = threadIdx.x;
    const float* t  = tok + (size_t)ids[row]  * DD;
    const float* sg = seg + (size_t)segs[row] * DD;
    float x[4]; float s = 0.f;
    #pragma unroll
    for (int i = 0; i < 4; i++) { int c = tid + i*256; x[i] = t[c] + sg[c]; s += x[i]; }
    __shared__ float red[256];
    red[tid] = s; __syncthreads();
    for (int o = 128; o > 0; o >>= 1) { if (tid < o) red[tid] += red[tid+o]; __syncthreads(); }
    float m = red[0] * (1.f / DD); __syncthreads();
    s = 0.f;
    #pragma unroll
    for (int i = 0; i < 4; i++) { float d = x[i] - m; s += d*d; }
    red[tid] = s; __syncthreads();
    for (int o = 128; o > 0; o >>= 1) { if (tid < o) red[tid] += red[tid+o]; __syncthreads(); }
    float inv = rsqrtf(red[0] * (1.f / DD) + 1e-12f);
    float mk = mask[row];
    #pragma unroll
    for (int i = 0; i < 4; i++) {
        int c = tid + i*256;
        float y = ((x[i] - m) * inv * g[c] + b[c]) * mk;
        size_t o = (size_t)row * DD + c;
        g_h[o] = y; hb[o] = __float2half(y);
    }
}

__global__ __launch_bounds__(256) void add_ln(
    const float* __restrict__ base, const float* __restrict__ addv,
    const float* __restrict__ g, const float* __restrict__ b,
    float* __restrict__ out)
{
    int row = blockIdx.x, tid = threadIdx.x;
    size_t off = (size_t)row * DD;
    float x[4]; float s = 0.f;
    #pragma unroll
    for (int i = 0; i < 4; i++) { int c = tid + i*256; x[i] = base[off+c] + addv[off+c]; s += x[i]; }
    __shared__ float red[256];
    red[tid] = s; __syncthreads();
    for (int o = 128; o > 0; o >>= 1) { if (tid < o) red[tid] += red[tid+o]; __syncthreads(); }
    float m = red[0] * (1.f / DD); __syncthreads();
    s = 0.f;
    #pragma unroll
    for (int i = 0; i < 4; i++) { float d = x[i] - m; s += d*d; }
    red[tid] = s; __syncthreads();
    for (int o = 128; o > 0; o >>= 1) { if (tid < o) red[tid] += red[tid+o]; __syncthreads(); }
    float inv = rsqrtf(red[0] * (1.f / DD) + 1e-12f);
    #pragma unroll
    for (int i = 0; i < 4; i++) {
        int c = tid + i*256;
        float y = (x[i] - m) * inv * g[c] + b[c];
        out[off + c] = y; hb[off + c] = __float2half(y);
    }
}

// ---------------- host --------------------------------------------------------------
extern "C" void kernel_launch(void* const* d_in, const int* in_sizes, int n_in,
                              void* d_out, int out_size)
{
    const int*   ids  = (const int*)d_in[0];
    const int*   segs = (const int*)d_in[1];
    const float* mask = (const float*)d_in[2];
    const float* tok  = (const float*)d_in[3];
    const float* seg  = (const float*)d_in[4];
    const float* elg  = (const float*)d_in[5];
    const float* elb  = (const float*)d_in[6];
    const float* rel  = (const float*)d_in[7];
    const float* Wq = (const float*)d_in[8],  *bq = (const float*)d_in[9];
    const float* Wk = (const float*)d_in[10], *bk = (const float*)d_in[11];
    const float* Wv = (const float*)d_in[12], *bv = (const float*)d_in[13];
    const float* Wo = (const float*)d_in[14], *bo = (const float*)d_in[15];
    const float* l1g = (const float*)d_in[16], *l1b = (const float*)d_in[17];
    const float* W1 = (const float*)d_in[18], *b1 = (const float*)d_in[19];
    const float* W2 = (const float*)d_in[20], *b2 = (const float*)d_in[21];
    const float* l2g = (const float*)d_in[22], *l2b = (const float*)d_in[23];

    float *h, *t2, *qb3, *pb2;
    cudaGetSymbolAddress((void**)&h,   g_h);
    cudaGetSymbolAddress((void**)&t2,  g_t2);
    cudaGetSymbolAddress((void**)&qb3, qkv_bias);
    cudaGetSymbolAddress((void**)&pb2, pos_bias);

    hf *hh,*qkv,*cx,*ff,*rl,*pos;
    hf *wqkv,*wpos,*wo_,*w1_,*w2_;
    hf *vt,*c2p,*p2c;
    cudaGetSymbolAddress((void**)&hh,  hb);
    cudaGetSymbolAddress((void**)&qkv, qkvb);  cudaGetSymbolAddress((void**)&cx, cxb);
    cudaGetSymbolAddress((void**)&ff,  ffb);   cudaGetSymbolAddress((void**)&rl, rlb);
    cudaGetSymbolAddress((void**)&pos, posb);
    cudaGetSymbolAddress((void**)&wqkv, wqkvt); cudaGetSymbolAddress((void**)&wpos, wpost);
    cudaGetSymbolAddress((void**)&wo_, wot);
    cudaGetSymbolAddress((void**)&w1_, w1t);   cudaGetSymbolAddress((void**)&w2_, w2t);
    cudaGetSymbolAddress((void**)&vt, vtb);
    cudaGetSymbolAddress((void**)&c2p, c2pb);  cudaGetSymbolAddress((void**)&p2c, p2cb);

    const int SM128 = 3 * (128*128 + 128*128);   // 98304
    const int SMATT = 66560;
    cudaFuncSetAttribute(gemm_mma<128,0>, cudaFuncAttributeMaxDynamicSharedMemorySize, SM128);
    cudaFuncSetAttribute(gemm_mma<128,1>, cudaFuncAttributeMaxDynamicSharedMemorySize, SM128);
    cudaFuncSetAttribute(fused_attn, cudaFuncAttributeMaxDynamicSharedMemorySize, SMATT);

    embed_ln<<<BS, 256>>>(ids, segs, mask, tok, seg, elg, elb);
    cvt_fp16<<<512, 256>>>(rel, rl, (size_t)PP * DD);

    dim3 tb(32, 8);
    const ll DD2 = (ll)DD * DD;
    const ll S2  = (ll)SS * SS;
    const ll SQ  = (ll)SS * 3 * DD;

    transpose_cvt<<<dim3(32,32,4),  tb>>>(Wq, DD2, wqkv,          3*DD2, DD, DD);
    transpose_cvt<<<dim3(32,32,4),  tb>>>(Wk, DD2, wqkv + DD2,    3*DD2, DD, DD);
    transpose_cvt<<<dim3(32,32,4),  tb>>>(Wv, DD2, wqkv + 2*DD2,  3*DD2, DD, DD);
    transpose_cvt<<<dim3(32,32,4),  tb>>>(Wk, DD2, wpos,          2*DD2, DD, DD);
    transpose_cvt<<<dim3(32,32,4),  tb>>>(Wq, DD2, wpos + DD2,    2*DD2, DD, DD);
    transpose_cvt<<<dim3(32,32,4),  tb>>>(Wo, DD2, wo_,           DD2,   DD, DD);
    transpose_cvt<<<dim3(128,32,4), tb>>>(W1, (ll)DD*FFD, w1_, (ll)FFD*DD, DD, FFD);
    transpose_cvt<<<dim3(32,128,4), tb>>>(W2, (ll)FFD*DD, w2_, (ll)DD*FFD, FFD, DD);
    concat_bias<<<dim3(4,1,4), 256>>>(bq, bk, bv, pb2, qb3);

    for (int l = 0; l < LL; l++) {
        const hf* wqkvL = wqkv + (size_t)l * 3 * DD2;
        const hf* wposL = wpos + (size_t)l * 2 * DD2;
        const hf* woL   = wo_  + (size_t)l * DD2;
        const hf* w1L   = w1_  + (size_t)l * FFD * DD;
        const hf* w2L   = w2_  + (size_t)l * DD * FFD;
        const float* qb3L = qb3 + (size_t)l * 3 * DD;
        const float* pb2L = pb2 + (size_t)l * 2 * DD;
        const float* bo_ = bo + (size_t)l*DD;
        const float* b1_ = b1 + (size_t)l*FFD;
        const float* b2_ = b2 + (size_t)l*DD;
        const float* g1 = l1g + (size_t)l*DD;    const float* be1 = l1b + (size_t)l*DD;
        const float* g2 = l2g + (size_t)l*DD;    const float* be2 = l2b + (size_t)l*DD;

        gemm_mma<128,0><<<dim3(24,32,1), 256, SM128>>>(hh,DD,0,0, wqkvL,DD,0,0,
            (float*)0, qkv, 3*DD,0,0, DD, qb3L);
        gemm_mma<128,0><<<dim3(16,8,1), 256, SM128>>>(rl,DD,0,0, wposL,DD,0,0,
            (float*)0, pos, 2*DD,0,0, DD, pb2L);

        const hf* q = qkv;
        const hf* k = qkv + DD;
        const hf* v = qkv + 2*DD;
        const hf* pk = pos;
        const hf* pq = pos + DD;

        gemm_mma<128,0><<<dim3(8,8,64), 256, SM128>>>(q,3*DD,SQ,64, pk,2*DD,0,64,
            (float*)0, c2p, PP,16*S2,S2, 64, (const float*)0);
        gemm_mma<128,0><<<dim3(8,8,64), 256, SM128>>>(k,3*DD,SQ,64, pq,2*DD,0,64,
            (float*)0, p2c, PP,16*S2,S2, 64, (const float*)0);

        vt_cvt<<<dim3(32,2,64), tb>>>(v, 3*DD, vt);

        fused_attn<<<dim3(8, 64), 256, SMATT>>>(qkv, vt, c2p, p2c, mask, cx);

        gemm_mma<128,0><<<dim3(8,32,1), 256, SM128>>>(cx,DD,0,0, woL,DD,0,0,
            t2, (hf*)0, DD,0,0, DD, bo_);
        add_ln<<<BS, 256>>>(h, t2, g1, be1, h);

        gemm_mma<128,1><<<dim3(32,32,1), 256, SM128>>>(hh,DD,0,0, w1L,DD,0,0,
            (float*)0, ff, FFD,0,0, DD, b1_);
        gemm_mma<128,0><<<dim3(8,32,1), 256, SM128>>>(ff,FFD,0,0, w2L,FFD,0,0,
            t2, (hf*)0, DD,0,0, FFD, b2_);
        add_ln<<<BS, 256>>>(h, t2, g2, be2,
                            (l == LL-1) ? (float*)d_out : h);
    }
}

// round 15
// speedup vs baseline: 1.2062x; 1.0140x over previous
#include <cuda_runtime.h>
#include <cuda_fp16.h>
#include <math.h>
#include <stdint.h>

#define BB 4
#define SS 1024
#define DD 1024
#define HH 16
#define DHH 64
#define FFD 4096
#define LL 4
#define PP 1024
#define SPAN_ 512
#define BS (BB*SS)

typedef long long ll;
typedef __half hf;

// ---------------- scratch ------------------------------------------------------
__device__ float g_h [BS*DD];
__device__ float g_t2[BS*DD];
__device__ float qkv_bias[4*3*DD];
__device__ float pos_bias[4*2*DD];

__device__ hf hb    [BS*DD];
__device__ hf qkvb  [(size_t)BS*3*DD];
__device__ hf cxb   [BS*DD];
__device__ hf ffb   [(size_t)BS*FFD];
__device__ hf rlb   [PP*DD];
__device__ hf posb  [(size_t)4*PP*2*DD];
__device__ hf wqkvt [(size_t)4*3*DD*DD];
__device__ hf wpost [(size_t)4*2*DD*DD];
__device__ hf wot   [(size_t)4*DD*DD];
__device__ hf w1t   [(size_t)4*FFD*DD];
__device__ hf w2t   [(size_t)4*DD*FFD];
__device__ hf vtb   [(size_t)BB*HH*DHH*SS];
__device__ hf c2pb  [(size_t)BB*HH*SS*PP];
__device__ hf p2cb  [(size_t)BB*HH*SS*PP];

// ---------------- helpers ------------------------------------------------------
__device__ __forceinline__ uint32_t smem_u32(const void* p) {
    uint32_t a;
    asm("{ .reg .u64 t; cvta.to.shared.u64 t, %1; cvt.u32.u64 %0, t; }" : "=r"(a) : "l"(p));
    return a;
}
__device__ __forceinline__ void cpa16(uint32_t dst, const void* src) {
    asm volatile("cp.async.cg.shared.global [%0], [%1], 16;" :: "r"(dst), "l"(src));
}
__device__ __forceinline__ void cpa_commit() { asm volatile("cp.async.commit_group;" ::: "memory"); }

__device__ __forceinline__ void ldm4(uint32_t* r, uint32_t addr) {
    asm volatile("ldmatrix.sync.aligned.m8n8.x4.shared.b16 {%0,%1,%2,%3}, [%4];"
                 : "=r"(r[0]), "=r"(r[1]), "=r"(r[2]), "=r"(r[3]) : "r"(addr));
}
__device__ __forceinline__ void mma16816(float* d, const uint32_t* a, const uint32_t* b) {
    asm volatile("mma.sync.aligned.m16n8k16.row.col.f32.f16.f16.f32 "
                 "{%0,%1,%2,%3}, {%4,%5,%6,%7}, {%8,%9}, {%0,%1,%2,%3};"
                 : "+f"(d[0]), "+f"(d[1]), "+f"(d[2]), "+f"(d[3])
                 : "r"(a[0]), "r"(a[1]), "r"(a[2]), "r"(a[3]), "r"(b[0]), "r"(b[1]));
}

// ---------------- fp16 mma.sync GEMM, 3-stage, 1 sync/chunk (validated) ----------
template <int NT, int ACT>
__global__ void __launch_bounds__(256) gemm_mma(
    const hf* __restrict__ A, int ldA, ll aSB, ll aSH,
    const hf* __restrict__ B, int ldB, ll bSB, ll bSH,
    float* __restrict__ C, hf* __restrict__ Ch,
    int ldC, ll cSB, ll cSH,
    int K, const float* __restrict__ bias)
{
    constexpr int ABY = 128 * 128;
    constexpr int BBY = NT * 128;
    constexpr int STAGE = ABY + BBY;
    constexpr int MT = (NT == 128) ? 4 : 2;
    constexpr int JT = 4;

    extern __shared__ char smem_raw[];
    uint32_t sbase = smem_u32(smem_raw);

    int tid = threadIdx.x, lane = tid & 31, wid = tid >> 5;
    int z = blockIdx.z;

    int warpM, warpN;
    if (NT == 128) { warpM = (wid & 1) * 64; warpN = (wid >> 1) * 32; }
    else           { warpM = (wid & 3) * 32; warpN = (wid >> 2) * 32; }

    const hf* Ab = A + (size_t)((ll)(z >> 4) * aSB + (ll)(z & 15) * aSH)
                     + (size_t)blockIdx.y * 128 * ldA;
    const hf* Bb = B + (size_t)((ll)(z >> 4) * bSB + (ll)(z & 15) * bSH)
                     + (size_t)blockIdx.x * NT * ldB;

    int NC = K >> 6;

    auto load_chunk = [&](int cn, int stage) {
        const hf* Ap = Ab + cn * 64;
        const hf* Bp = Bb + cn * 64;
        uint32_t Ad = sbase + stage * STAGE;
        uint32_t Bd = Ad + ABY;
        #pragma unroll
        for (int i = 0; i < 4; i++) {
            int idx = tid + i * 256;
            int r = idx >> 3, c = idx & 7;
            cpa16(Ad + r * 128 + ((c ^ (r & 7)) << 4), Ap + (size_t)r * ldA + c * 8);
        }
        #pragma unroll
        for (int i = 0; i < NT / 32; i++) {
            int idx = tid + i * 256;
            int r = idx >> 3, c = idx & 7;
            cpa16(Bd + r * 128 + ((c ^ (r & 7)) << 4), Bp + (size_t)r * ldB + c * 8);
        }
        cpa_commit();
    };

    float acc[MT][JT][4];
    #pragma unroll
    for (int i = 0; i < MT; i++)
        #pragma unroll
        for (int j = 0; j < JT; j++)
            #pragma unroll
            for (int e = 0; e < 4; e++) acc[i][j][e] = 0.f;

    load_chunk(0, 0);
    if (NC > 1) load_chunk(1, 1);

    for (int c = 0; c < NC; c++) {
        if (c + 1 < NC) asm volatile("cp.async.wait_group 1;" ::: "memory");
        else            asm volatile("cp.async.wait_group 0;" ::: "memory");
        __syncthreads();

        uint32_t Abuf = sbase + (c % 3) * STAGE;
        uint32_t Bbuf = Abuf + ABY;
        #pragma unroll
        for (int ks = 0; ks < 4; ks++) {
            uint32_t a[MT][4], b[JT][2];
            #pragma unroll
            for (int i = 0; i < MT; i++) {
                int row = warpM + i * 16 + (lane & 15);
                int cc = ks * 2 + (lane >> 4);
                ldm4(a[i], Abuf + row * 128 + (((cc ^ (row & 7)) << 4)));
            }
            #pragma unroll
            for (int j = 0; j < JT / 2; j++) {
                int n = warpN + j * 16 + ((lane >> 4) << 3) + (lane & 7);
                int cc = ks * 2 + ((lane >> 3) & 1);
                uint32_t t[4];
                ldm4(t, Bbuf + n * 128 + (((cc ^ (n & 7)) << 4)));
                b[j*2][0] = t[0];   b[j*2][1] = t[1];
                b[j*2+1][0] = t[2]; b[j*2+1][1] = t[3];
            }
            #pragma unroll
            for (int i = 0; i < MT; i++)
                #pragma unroll
                for (int j = 0; j < JT; j++)
                    mma16816(acc[i][j], a[i], b[j]);
        }
        if (c + 2 < NC) load_chunk(c + 2, (c + 2) % 3);
    }

    ll cO = (ll)(z >> 4) * cSB + (ll)(z & 15) * cSH;
    int m0 = blockIdx.y * 128, n0 = blockIdx.x * NT;
    int quad = lane >> 2, l4 = lane & 3;

    #pragma unroll
    for (int i = 0; i < MT; i++) {
        int r0 = m0 + warpM + i * 16 + quad;
        #pragma unroll
        for (int j = 0; j < JT; j++) {
            int col = n0 + warpN + j * 8 + l4 * 2;
            float b0 = 0.f, b1 = 0.f;
            if (bias) { b0 = bias[col]; b1 = bias[col + 1]; }
            #pragma unroll
            for (int half = 0; half < 2; half++) {
                int row = r0 + half * 8;
                float v0 = acc[i][j][half*2 + 0] + b0;
                float v1 = acc[i][j][half*2 + 1] + b1;
                if (ACT) {
                    v0 = 0.5f * v0 * (1.f + erff(v0 * 0.70710678118654752f));
                    v1 = 0.5f * v1 * (1.f + erff(v1 * 0.70710678118654752f));
                }
                size_t base = (size_t)cO + (size_t)row * ldC + col;
                if (C) *(float2*)(C + base) = make_float2(v0, v1);
                if (Ch) *(__half2*)(Ch + base) =
                    __halves2half2(__float2half(v0), __float2half(v1));
            }
        }
    }
}

// ---------------- fused attention: softmax(qk^T + bias) @ V (validated R14) -----
__global__ void __launch_bounds__(256) fused_attn(
    const hf* __restrict__ qkv, const hf* __restrict__ vt,
    const hf* __restrict__ c2p, const hf* __restrict__ p2c,
    const float* __restrict__ mask, hf* __restrict__ ctx)
{
    extern __shared__ char smem_raw[];
    uint32_t sbase = smem_u32(smem_raw);
    float* factorArr = (float*)(smem_raw + 65536);
    float* linvArr   = (float*)(smem_raw + 66048);

    int tid = threadIdx.x, lane = tid & 31, wid = tid >> 5;
    int quad = lane >> 2, l4 = lane & 3;
    int q0 = blockIdx.x * 128, bh = blockIdx.y;
    int b = bh >> 4, h = bh & 15;
    const float scale = 0.07216878364870323f;

    const hf* qsrc = qkv + (size_t)(b*SS + q0) * (3*DD) + h*64;
    const hf* ksrc = qkv + (size_t)(b*SS) * (3*DD) + DD + h*64;
    const hf* vsrc = vt  + (size_t)bh * 64 * SS;
    const hf* c2bh = c2p + (size_t)bh * SS * PP;
    const hf* p2bh = p2c + (size_t)bh * SS * PP;
    const float* mk = mask + b * SS;

    for (int i = tid; i < 1024; i += 256) {
        int r = i >> 3, c = i & 7;
        cpa16(sbase + r*128 + ((c^(r&7))<<4), qsrc + (size_t)r*(3*DD) + c*8);
    }
    for (int i = tid; i < 512; i += 256) {
        int r = i >> 3, c = i & 7;
        cpa16(sbase + 16384 + r*128 + ((c^(r&7))<<4), ksrc + (size_t)r*(3*DD) + c*8);
    }
    cpa_commit();

    float accO[2][4][4];
    #pragma unroll
    for (int i = 0; i < 2; i++)
        #pragma unroll
        for (int j = 0; j < 4; j++)
            #pragma unroll
            for (int e = 0; e < 4; e++) accO[i][j][e] = 0.f;
    float mreg[2] = {-1e30f, -1e30f};
    float lreg[2] = {0.f, 0.f};

    int r0 = wid * 16 + quad;

    for (int t = 0; t < 16; t++) {
        asm volatile("cp.async.wait_group 0;" ::: "memory");
        __syncthreads();
        int k0 = t * 64;

        uint32_t Vb = sbase + 32768 + (t & 1) * 8192;
        for (int i = tid; i < 512; i += 256) {
            int r = i >> 3, c = i & 7;
            cpa16(Vb + r*128 + ((c^(r&7))<<4), vsrc + (size_t)r*SS + k0 + c*8);
        }
        cpa_commit();

        uint32_t Kb = sbase + 16384 + (t & 1) * 8192;
        float sacc[8][4];
        #pragma unroll
        for (int j = 0; j < 8; j++)
            #pragma unroll
            for (int e = 0; e < 4; e++) sacc[j][e] = 0.f;
        #pragma unroll
        for (int ks = 0; ks < 4; ks++) {
            uint32_t a[4], bb[8][2];
            int row = wid * 16 + (lane & 15);
            int cc = ks * 2 + (lane >> 4);
            ldm4(a, sbase + row*128 + ((cc^(row&7))<<4));
            #pragma unroll
            for (int j = 0; j < 4; j++) {
                int n = j * 16 + ((lane >> 4) << 3) + (lane & 7);
                int c2 = ks * 2 + ((lane >> 3) & 1);
                uint32_t t4[4];
                ldm4(t4, Kb + n*128 + ((c2^(n&7))<<4));
                bb[j*2][0] = t4[0];   bb[j*2][1] = t4[1];
                bb[j*2+1][0] = t4[2]; bb[j*2+1][1] = t4[3];
            }
            #pragma unroll
            for (int j = 0; j < 8; j++) mma16816(sacc[j], a, bb[j]);
        }

        if (t + 1 < 16) {
            uint32_t Kn = sbase + 16384 + ((t + 1) & 1) * 8192;
            for (int i = tid; i < 512; i += 256) {
                int r = i >> 3, c = i & 7;
                cpa16(Kn + r*128 + ((c^(r&7))<<4),
                      ksrc + (size_t)(k0 + 64 + r)*(3*DD) + c*8);
            }
            cpa_commit();
        }

        #pragma unroll
        for (int half = 0; half < 2; half++) {
            int row = r0 + half * 8;
            int qg = q0 + row;
            const hf* c2r = c2bh + (size_t)qg * PP;
            float v[16];
            float tmax = -1e30f;
            #pragma unroll
            for (int j = 0; j < 8; j++) {
                #pragma unroll
                for (int e = 0; e < 2; e++) {
                    int col = k0 + j*8 + l4*2 + e;
                    int idx = min(max(qg - col + SPAN_, 0), PP - 1);
                    float s = sacc[j][half*2 + e]
                            + __half2float(c2r[idx])
                            + __half2float(p2bh[(size_t)col * PP + idx]);
                    float vv = s * scale + (1.f - mk[col]) * -1e9f;
                    v[j*2 + e] = vv;
                    tmax = fmaxf(tmax, vv);
                }
            }
            tmax = fmaxf(tmax, __shfl_xor_sync(0xFFFFFFFFu, tmax, 1));
            tmax = fmaxf(tmax, __shfl_xor_sync(0xFFFFFFFFu, tmax, 2));
            float mnew = fmaxf(mreg[half], tmax);
            float fac = __expf(mreg[half] - mnew);
            mreg[half] = mnew;
            float sum = 0.f;
            #pragma unroll
            for (int j = 0; j < 8; j++) {
                float p0 = __expf(v[j*2]     - mnew);
                float p1 = __expf(v[j*2 + 1] - mnew);
                sum += p0 + p1;
                int col0 = j*8 + l4*2;
                int u = col0 >> 3;
                uint32_t addr = sbase + 49152 + row*128
                              + ((u ^ (row & 7)) << 4) + (col0 & 7) * 2;
                *(__half2*)(smem_raw + (addr - sbase)) =
                    __halves2half2(__float2half(p0), __float2half(p1));
            }
            sum += __shfl_xor_sync(0xFFFFFFFFu, sum, 1);
            sum += __shfl_xor_sync(0xFFFFFFFFu, sum, 2);
            lreg[half] = lreg[half] * fac + sum;
            if (l4 == 0) factorArr[row] = fac;
        }

        if (t + 1 < 16) asm volatile("cp.async.wait_group 1;" ::: "memory");
        else            asm volatile("cp.async.wait_group 0;" ::: "memory");
        __syncthreads();

        int oM = (wid & 3) * 32, oN = (wid >> 2) * 32;
        #pragma unroll
        for (int i = 0; i < 2; i++) {
            #pragma unroll
            for (int half = 0; half < 2; half++) {
                float f = factorArr[oM + i*16 + quad + half*8];
                #pragma unroll
                for (int j = 0; j < 4; j++) {
                    accO[i][j][half*2 + 0] *= f;
                    accO[i][j][half*2 + 1] *= f;
                }
            }
        }
        #pragma unroll
        for (int ks = 0; ks < 4; ks++) {
            uint32_t a[2][4], bb[4][2];
            #pragma unroll
            for (int i = 0; i < 2; i++) {
                int row = oM + i*16 + (lane & 15);
                int cc = ks * 2 + (lane >> 4);
                ldm4(a[i], sbase + 49152 + row*128 + ((cc^(row&7))<<4));
            }
            #pragma unroll
            for (int j = 0; j < 2; j++) {
                int n = oN + j*16 + ((lane >> 4) << 3) + (lane & 7);
                int c2 = ks * 2 + ((lane >> 3) & 1);
                uint32_t t4[4];
                ldm4(t4, Vb + n*128 + ((c2^(n&7))<<4));
                bb[j*2][0] = t4[0];   bb[j*2][1] = t4[1];
                bb[j*2+1][0] = t4[2]; bb[j*2+1][1] = t4[3];
            }
            #pragma unroll
            for (int i = 0; i < 2; i++)
                #pragma unroll
                for (int j = 0; j < 4; j++)
                    mma16816(accO[i][j], a[i], bb[j]);
        }
    }

    if (l4 == 0) {
        linvArr[r0]     = 1.f / lreg[0];
        linvArr[r0 + 8] = 1.f / lreg[1];
    }
    __syncthreads();

    int oM = (wid & 3) * 32, oN = (wid >> 2) * 32;
    #pragma unroll
    for (int i = 0; i < 2; i++) {
        #pragma unroll
        for (int half = 0; half < 2; half++) {
            int row = oM + i*16 + quad + half*8;
            float inv = linvArr[row];
            size_t base = ((size_t)(b*SS + q0 + row)) * DD + h*64 + oN;
            #pragma unroll
            for (int j = 0; j < 4; j++) {
                float v0 = accO[i][j][half*2 + 0] * inv;
                float v1 = accO[i][j][half*2 + 1] * inv;
                *(__half2*)(ctx + base + j*8 + l4*2) =
                    __halves2half2(__float2half(v0), __float2half(v1));
            }
        }
    }
}

// ---------------- converters -----------------------------------------------------
__global__ __launch_bounds__(256) void cvt_fp16(
    const float* __restrict__ in, hf* __restrict__ out, size_t n)
{
    for (size_t i = blockIdx.x * 256ull + threadIdx.x; i < n; i += gridDim.x * 256ull)
        out[i] = __float2half(in[i]);
}

__global__ void concat_bias(const float* bq, const float* bk, const float* bv,
                            float* out2, float* out3)
{
    int l = blockIdx.z;
    const float* a = bq + (size_t)l * DD;
    const float* b = bk + (size_t)l * DD;
    const float* c = bv + (size_t)l * DD;
    float* o3 = out3 + (size_t)l * 3 * DD;
    float* o2 = out2 + (size_t)l * 2 * DD;
    int i = blockIdx.x * 256 + threadIdx.x;
    if (i < DD) {
        o3[i] = a[i]; o3[i + DD] = b[i]; o3[i + 2*DD] = c[i];
        o2[i] = b[i]; o2[i + DD] = a[i];
    }
}

__global__ void transpose_cvt(
    const float* __restrict__ in, ll inLS, hf* __restrict__ out, ll outLS,
    int K, int N)
{
    in  += (size_t)blockIdx.z * inLS;
    out += (size_t)blockIdx.z * outLS;
    __shared__ float t[32][33];
    int k0 = blockIdx.y * 32, n0 = blockIdx.x * 32;
    int tx = threadIdx.x, ty = threadIdx.y;
    for (int i = ty; i < 32; i += 8)
        t[i][tx] = in[(size_t)(k0 + i) * N + n0 + tx];
    __syncthreads();
    for (int i = ty; i < 32; i += 8)
        out[(size_t)(n0 + i) * K + k0 + tx] = __float2half(t[tx][i]);
}

__global__ void vt_cvt(const hf* __restrict__ v, int ldv, hf* __restrict__ out)
{
    __shared__ hf t[32][33];
    int bh = blockIdx.z, b = bh >> 4, h = bh & 15;
    int s0 = blockIdx.x * 32, d0 = blockIdx.y * 32;
    int tx = threadIdx.x, ty = threadIdx.y;
    for (int i = ty; i < 32; i += 8)
        t[i][tx] = v[((size_t)b * SS + s0 + i) * ldv + h * 64 + d0 + tx];
    __syncthreads();
    for (int i = ty; i < 32; i += 8)
        out[((size_t)bh * 64 + d0 + i) * SS + s0 + tx] = t[tx][i];
}

// ---------------- embedding / LN ----------------------------------------------
__global__ __launch_bounds__(256) void embed_ln(
    const int* __restrict__ ids, const int* __restrict__ segs,
    const float* __restrict__ mask, const float* __restrict__ tok,
    const float* __restrict__ seg, const float* __restrict__ g,
    const float* __restrict__ b)
{
    int row = blockIdx.x, tid = threadIdx.x;
    const float* t  = tok + (size_t)ids[row]  * DD;
    const float* sg = seg + (size_t)segs[row] * DD;
    float x[4]; float s = 0.f;
    #pragma unroll
    for (int i = 0; i < 4; i++) { int c = tid + i*256; x[i] = t[c] + sg[c]; s += x[i]; }
    __shared__ float red[256];
    red[tid] = s; __syncthreads();
    for (int o = 128; o > 0; o >>= 1) { if (tid < o) red[tid] += red[tid+o]; __syncthreads(); }
    float m = red[0] * (1.f / DD); __syncthreads();
    s = 0.f;
    #pragma unroll
    for (int i = 0; i < 4; i++) { float d = x[i] - m; s += d*d; }
    red[tid] = s; __syncthreads();
    for (int o = 128; o > 0; o >>= 1) { if (tid < o) red[tid] += red[tid+o]; __syncthreads(); }
    float inv = rsqrtf(red[0] * (1.f / DD) + 1e-12f);
    float mk = mask[row];
    #pragma unroll
    for (int i = 0; i < 4; i++) {
        int c = tid + i*256;
        float y = ((x[i] - m) * inv * g[c] + b[c]) * mk;
        size_t o = (size_t)row * DD + c;
        g_h[o] = y; hb[o] = __float2half(y);
    }
}

__global__ __launch_bounds__(256) void add_ln(
    const float* __restrict__ base, const float* __restrict__ addv,
    const float* __restrict__ g, const float* __restrict__ b,
    float* __restrict__ out)
{
    int row = blockIdx.x, tid = threadIdx.x;
    size_t off = (size_t)row * DD;
    float x[4]; float s = 0.f;
    #pragma unroll
    for (int i = 0; i < 4; i++) { int c = tid + i*256; x[i] = base[off+c] + addv[off+c]; s += x[i]; }
    __shared__ float red[256];
    red[tid] = s; __syncthreads();
    for (int o = 128; o > 0; o >>= 1) { if (tid < o) red[tid] += red[tid+o]; __syncthreads(); }
    float m = red[0] * (1.f / DD); __syncthreads();
    s = 0.f;
    #pragma unroll
    for (int i = 0; i < 4; i++) { float d = x[i] - m; s += d*d; }
    red[tid] = s; __syncthreads();
    for (int o = 128; o > 0; o >>= 1) { if (tid < o) red[tid] += red[tid+o]; __syncthreads(); }
    float inv = rsqrtf(red[0] * (1.f / DD) + 1e-12f);
    #pragma unroll
    for (int i = 0; i < 4; i++) {
        int c = tid + i*256;
        float y = (x[i] - m) * inv * g[c] + b[c];
        out[off + c] = y; hb[off + c] = __float2half(y);
    }
}

// ---------------- host --------------------------------------------------------------
extern "C" void kernel_launch(void* const* d_in, const int* in_sizes, int n_in,
                              void* d_out, int out_size)
{
    const int*   ids  = (const int*)d_in[0];
    const int*   segs = (const int*)d_in[1];
    const float* mask = (const float*)d_in[2];
    const float* tok  = (const float*)d_in[3];
    const float* seg  = (const float*)d_in[4];
    const float* elg  = (const float*)d_in[5];
    const float* elb  = (const float*)d_in[6];
    const float* rel  = (const float*)d_in[7];
    const float* Wq = (const float*)d_in[8],  *bq = (const float*)d_in[9];
    const float* Wk = (const float*)d_in[10], *bk = (const float*)d_in[11];
    const float* Wv = (const float*)d_in[12], *bv = (const float*)d_in[13];
    const float* Wo = (const float*)d_in[14], *bo = (const float*)d_in[15];
    const float* l1g = (const float*)d_in[16], *l1b = (const float*)d_in[17];
    const float* W1 = (const float*)d_in[18], *b1 = (const float*)d_in[19];
    const float* W2 = (const float*)d_in[20], *b2 = (const float*)d_in[21];
    const float* l2g = (const float*)d_in[22], *l2b = (const float*)d_in[23];

    float *h, *t2, *qb3, *pb2;
    cudaGetSymbolAddress((void**)&h,   g_h);
    cudaGetSymbolAddress((void**)&t2,  g_t2);
    cudaGetSymbolAddress((void**)&qb3, qkv_bias);
    cudaGetSymbolAddress((void**)&pb2, pos_bias);

    hf *hh,*qkv,*cx,*ff,*rl,*pos;
    hf *wqkv,*wpos,*wo_,*w1_,*w2_;
    hf *vt,*c2p,*p2c;
    cudaGetSymbolAddress((void**)&hh,  hb);
    cudaGetSymbolAddress((void**)&qkv, qkvb);  cudaGetSymbolAddress((void**)&cx, cxb);
    cudaGetSymbolAddress((void**)&ff,  ffb);   cudaGetSymbolAddress((void**)&rl, rlb);
    cudaGetSymbolAddress((void**)&pos, posb);
    cudaGetSymbolAddress((void**)&wqkv, wqkvt); cudaGetSymbolAddress((void**)&wpos, wpost);
    cudaGetSymbolAddress((void**)&wo_, wot);
    cudaGetSymbolAddress((void**)&w1_, w1t);   cudaGetSymbolAddress((void**)&w2_, w2t);
    cudaGetSymbolAddress((void**)&vt, vtb);
    cudaGetSymbolAddress((void**)&c2p, c2pb);  cudaGetSymbolAddress((void**)&p2c, p2cb);

    const int SM128 = 3 * (128*128 + 128*128);   // 98304
    const int SMATT = 66560;
    cudaFuncSetAttribute(gemm_mma<128,0>, cudaFuncAttributeMaxDynamicSharedMemorySize, SM128);
    cudaFuncSetAttribute(gemm_mma<128,1>, cudaFuncAttributeMaxDynamicSharedMemorySize, SM128);
    cudaFuncSetAttribute(fused_attn, cudaFuncAttributeMaxDynamicSharedMemorySize, SMATT);

    // second stream + events (capture-legal fork/join off the legacy stream)
    cudaStream_t s2;
    cudaStreamCreate(&s2);
    cudaEvent_t evPosIn, evPosOut, evQ[LL], evV[LL];
    cudaEventCreateWithFlags(&evPosIn,  cudaEventDisableTiming);
    cudaEventCreateWithFlags(&evPosOut, cudaEventDisableTiming);
    for (int l = 0; l < LL; l++) {
        cudaEventCreateWithFlags(&evQ[l], cudaEventDisableTiming);
        cudaEventCreateWithFlags(&evV[l], cudaEventDisableTiming);
    }

    dim3 tb(32, 8);
    const ll DD2 = (ll)DD * DD;
    const ll S2  = (ll)SS * SS;
    const ll SQ  = (ll)SS * 3 * DD;
    const ll POSL = (ll)PP * 2 * DD;

    // startup (legacy stream): embed + rel cvt + pos weights first
    cvt_fp16<<<512, 256>>>(rel, rl, (size_t)PP * DD);
    transpose_cvt<<<dim3(32,32,4),  tb>>>(Wk, DD2, wpos,          2*DD2, DD, DD);
    transpose_cvt<<<dim3(32,32,4),  tb>>>(Wq, DD2, wpos + DD2,    2*DD2, DD, DD);
    concat_bias<<<dim3(4,1,4), 256>>>(bq, bk, bv, pb2, qb3);
    cudaEventRecord(evPosIn, 0);

    // s2: all 4 layers' pos GEMMs concurrent with remaining startup + layer-0 QKV
    cudaStreamWaitEvent(s2, evPosIn, 0);
    for (int l = 0; l < LL; l++)
        gemm_mma<128,0><<<dim3(16,8,1), 256, SM128, s2>>>(
            rl,DD,0,0, wpos + (size_t)l*2*DD2,DD,0,0,
            (float*)0, pos + (size_t)l*POSL, 2*DD,0,0, DD, pb2 + (size_t)l*2*DD);
    cudaEventRecord(evPosOut, s2);

    embed_ln<<<BS, 256>>>(ids, segs, mask, tok, seg, elg, elb);
    transpose_cvt<<<dim3(32,32,4),  tb>>>(Wq, DD2, wqkv,          3*DD2, DD, DD);
    transpose_cvt<<<dim3(32,32,4),  tb>>>(Wk, DD2, wqkv + DD2,    3*DD2, DD, DD);
    transpose_cvt<<<dim3(32,32,4),  tb>>>(Wv, DD2, wqkv + 2*DD2,  3*DD2, DD, DD);
    transpose_cvt<<<dim3(32,32,4),  tb>>>(Wo, DD2, wo_,           DD2,   DD, DD);
    transpose_cvt<<<dim3(128,32,4), tb>>>(W1, (ll)DD*FFD, w1_, (ll)FFD*DD, DD, FFD);
    transpose_cvt<<<dim3(32,128,4), tb>>>(W2, (ll)FFD*DD, w2_, (ll)DD*FFD, FFD, DD);

    cudaStreamWaitEvent(0, evPosOut, 0);

    for (int l = 0; l < LL; l++) {
        const hf* wqkvL = wqkv + (size_t)l * 3 * DD2;
        const hf* woL   = wo_  + (size_t)l * DD2;
        const hf* w1L   = w1_  + (size_t)l * FFD * DD;
        const hf* w2L   = w2_  + (size_t)l * DD * FFD;
        const float* qb3L = qb3 + (size_t)l * 3 * DD;
        const float* bo_ = bo + (size_t)l*DD;
        const float* b1_ = b1 + (size_t)l*FFD;
        const float* b2_ = b2 + (size_t)l*DD;
        const float* g1 = l1g + (size_t)l*DD;    const float* be1 = l1b + (size_t)l*DD;
        const float* g2 = l2g + (size_t)l*DD;    const float* be2 = l2b + (size_t)l*DD;

        gemm_mma<128,0><<<dim3(24,32,1), 256, SM128>>>(hh,DD,0,0, wqkvL,DD,0,0,
            (float*)0, qkv, 3*DD,0,0, DD, qb3L);
        cudaEventRecord(evQ[l], 0);

        const hf* q = qkv;
        const hf* k = qkv + DD;
        const hf* v = qkv + 2*DD;
        const hf* pk = pos + (size_t)l * POSL;
        const hf* pq = pk + DD;

        // vt_cvt on s2, concurrent with c2p/p2c GEMMs on main stream
        cudaStreamWaitEvent(s2, evQ[l], 0);
        vt_cvt<<<dim3(32,2,64), tb, 0, s2>>>(v, 3*DD, vt);
        cudaEventRecord(evV[l], s2);

        gemm_mma<128,0><<<dim3(8,8,64), 256, SM128>>>(q,3*DD,SQ,64, pk,2*DD,0,64,
            (float*)0, c2p, PP,16*S2,S2, 64, (const float*)0);
        gemm_mma<128,0><<<dim3(8,8,64), 256, SM128>>>(k,3*DD,SQ,64, pq,2*DD,0,64,
            (float*)0, p2c, PP,16*S2,S2, 64, (const float*)0);

        cudaStreamWaitEvent(0, evV[l], 0);
        fused_attn<<<dim3(8, 64), 256, SMATT>>>(qkv, vt, c2p, p2c, mask, cx);

        gemm_mma<128,0><<<dim3(8,32,1), 256, SM128>>>(cx,DD,0,0, woL,DD,0,0,
            t2, (hf*)0, DD,0,0, DD, bo_);
        add_ln<<<BS, 256>>>(h, t2, g1, be1, h);

        gemm_mma<128,1><<<dim3(32,32,1), 256, SM128>>>(hh,DD,0,0, w1L,DD,0,0,
            (float*)0, ff, FFD,0,0, DD, b1_);
        gemm_mma<128,0><<<dim3(8,32,1), 256, SM128>>>(ff,FFD,0,0, w2L,FFD,0,0,
            t2, (hf*)0, DD,0,0, FFD, b2_);
        add_ln<<<BS, 256>>>(h, t2, g2, be2,
                            (l == LL-1) ? (float*)d_out : h);
    }
}

// round 16
// speedup vs baseline: 1.2465x; 1.0334x over previous
#include <cuda_runtime.h>
#include <cuda_fp16.h>
#include <math.h>
#include <stdint.h>

#define BB 4
#define SS 1024
#define DD 1024
#define HH 16
#define DHH 64
#define FFD 4096
#define LL 4
#define PP 1024
#define SPAN_ 512
#define BS (BB*SS)

typedef long long ll;
typedef __half hf;

// ---------------- scratch ------------------------------------------------------
__device__ float g_h [BS*DD];
__device__ float g_t2[BS*DD];
__device__ float qkv_bias[4*3*DD];
__device__ float pos_bias[4*2*DD];

__device__ hf hb    [BS*DD];
__device__ hf qkvb  [(size_t)BS*3*DD];
__device__ hf cxb   [BS*DD];
__device__ hf ffb   [(size_t)BS*FFD];
__device__ hf rlb   [PP*DD];
__device__ hf posb  [(size_t)4*PP*2*DD];
__device__ hf wqkvt [(size_t)4*3*DD*DD];
__device__ hf wpost [(size_t)4*2*DD*DD];
__device__ hf wot   [(size_t)4*DD*DD];
__device__ hf w1t   [(size_t)4*FFD*DD];
__device__ hf w2t   [(size_t)4*DD*FFD];
__device__ hf vtb   [(size_t)BB*HH*DHH*SS];
__device__ hf c2pb  [(size_t)BB*HH*SS*PP];
__device__ hf p2cb  [(size_t)BB*HH*SS*PP];

// ---------------- helpers ------------------------------------------------------
__device__ __forceinline__ uint32_t smem_u32(const void* p) {
    uint32_t a;
    asm("{ .reg .u64 t; cvta.to.shared.u64 t, %1; cvt.u32.u64 %0, t; }" : "=r"(a) : "l"(p));
    return a;
}
__device__ __forceinline__ void cpa16(uint32_t dst, const void* src) {
    asm volatile("cp.async.cg.shared.global [%0], [%1], 16;" :: "r"(dst), "l"(src));
}
__device__ __forceinline__ void cpa_commit() { asm volatile("cp.async.commit_group;" ::: "memory"); }

__device__ __forceinline__ void ldm4(uint32_t* r, uint32_t addr) {
    asm volatile("ldmatrix.sync.aligned.m8n8.x4.shared.b16 {%0,%1,%2,%3}, [%4];"
                 : "=r"(r[0]), "=r"(r[1]), "=r"(r[2]), "=r"(r[3]) : "r"(addr));
}
__device__ __forceinline__ void mma16816(float* d, const uint32_t* a, const uint32_t* b) {
    asm volatile("mma.sync.aligned.m16n8k16.row.col.f32.f16.f16.f32 "
                 "{%0,%1,%2,%3}, {%4,%5,%6,%7}, {%8,%9}, {%0,%1,%2,%3};"
                 : "+f"(d[0]), "+f"(d[1]), "+f"(d[2]), "+f"(d[3])
                 : "r"(a[0]), "r"(a[1]), "r"(a[2]), "r"(a[3]), "r"(b[0]), "r"(b[1]));
}

// ---------------- fp16 mma.sync GEMM, 3-stage, 1 sync/chunk (validated) ----------
template <int NT, int ACT>
__global__ void __launch_bounds__(256) gemm_mma(
    const hf* __restrict__ A, int ldA, ll aSB, ll aSH,
    const hf* __restrict__ B, int ldB, ll bSB, ll bSH,
    float* __restrict__ C, hf* __restrict__ Ch,
    int ldC, ll cSB, ll cSH,
    int K, const float* __restrict__ bias)
{
    constexpr int ABY = 128 * 128;
    constexpr int BBY = NT * 128;
    constexpr int STAGE = ABY + BBY;
    constexpr int MT = (NT == 128) ? 4 : 2;
    constexpr int JT = 4;

    extern __shared__ char smem_raw[];
    uint32_t sbase = smem_u32(smem_raw);

    int tid = threadIdx.x, lane = tid & 31, wid = tid >> 5;
    int z = blockIdx.z;

    int warpM, warpN;
    if (NT == 128) { warpM = (wid & 1) * 64; warpN = (wid >> 1) * 32; }
    else           { warpM = (wid & 3) * 32; warpN = (wid >> 2) * 32; }

    const hf* Ab = A + (size_t)((ll)(z >> 4) * aSB + (ll)(z & 15) * aSH)
                     + (size_t)blockIdx.y * 128 * ldA;
    const hf* Bb = B + (size_t)((ll)(z >> 4) * bSB + (ll)(z & 15) * bSH)
                     + (size_t)blockIdx.x * NT * ldB;

    int NC = K >> 6;

    auto load_chunk = [&](int cn, int stage) {
        const hf* Ap = Ab + cn * 64;
        const hf* Bp = Bb + cn * 64;
        uint32_t Ad = sbase + stage * STAGE;
        uint32_t Bd = Ad + ABY;
        #pragma unroll
        for (int i = 0; i < 4; i++) {
            int idx = tid + i * 256;
            int r = idx >> 3, c = idx & 7;
            cpa16(Ad + r * 128 + ((c ^ (r & 7)) << 4), Ap + (size_t)r * ldA + c * 8);
        }
        #pragma unroll
        for (int i = 0; i < NT / 32; i++) {
            int idx = tid + i * 256;
            int r = idx >> 3, c = idx & 7;
            cpa16(Bd + r * 128 + ((c ^ (r & 7)) << 4), Bp + (size_t)r * ldB + c * 8);
        }
        cpa_commit();
    };

    float acc[MT][JT][4];
    #pragma unroll
    for (int i = 0; i < MT; i++)
        #pragma unroll
        for (int j = 0; j < JT; j++)
            #pragma unroll
            for (int e = 0; e < 4; e++) acc[i][j][e] = 0.f;

    load_chunk(0, 0);
    if (NC > 1) load_chunk(1, 1);

    for (int c = 0; c < NC; c++) {
        if (c + 1 < NC) asm volatile("cp.async.wait_group 1;" ::: "memory");
        else            asm volatile("cp.async.wait_group 0;" ::: "memory");
        __syncthreads();

        uint32_t Abuf = sbase + (c % 3) * STAGE;
        uint32_t Bbuf = Abuf + ABY;
        #pragma unroll
        for (int ks = 0; ks < 4; ks++) {
            uint32_t a[MT][4], b[JT][2];
            #pragma unroll
            for (int i = 0; i < MT; i++) {
                int row = warpM + i * 16 + (lane & 15);
                int cc = ks * 2 + (lane >> 4);
                ldm4(a[i], Abuf + row * 128 + (((cc ^ (row & 7)) << 4)));
            }
            #pragma unroll
            for (int j = 0; j < JT / 2; j++) {
                int n = warpN + j * 16 + ((lane >> 4) << 3) + (lane & 7);
                int cc = ks * 2 + ((lane >> 3) & 1);
                uint32_t t[4];
                ldm4(t, Bbuf + n * 128 + (((cc ^ (n & 7)) << 4)));
                b[j*2][0] = t[0];   b[j*2][1] = t[1];
                b[j*2+1][0] = t[2]; b[j*2+1][1] = t[3];
            }
            #pragma unroll
            for (int i = 0; i < MT; i++)
                #pragma unroll
                for (int j = 0; j < JT; j++)
                    mma16816(acc[i][j], a[i], b[j]);
        }
        if (c + 2 < NC) load_chunk(c + 2, (c + 2) % 3);
    }

    ll cO = (ll)(z >> 4) * cSB + (ll)(z & 15) * cSH;
    int m0 = blockIdx.y * 128, n0 = blockIdx.x * NT;
    int quad = lane >> 2, l4 = lane & 3;

    #pragma unroll
    for (int i = 0; i < MT; i++) {
        int r0 = m0 + warpM + i * 16 + quad;
        #pragma unroll
        for (int j = 0; j < JT; j++) {
            int col = n0 + warpN + j * 8 + l4 * 2;
            float b0 = 0.f, b1 = 0.f;
            if (bias) { b0 = bias[col]; b1 = bias[col + 1]; }
            #pragma unroll
            for (int half = 0; half < 2; half++) {
                int row = r0 + half * 8;
                float v0 = acc[i][j][half*2 + 0] + b0;
                float v1 = acc[i][j][half*2 + 1] + b1;
                if (ACT) {
                    v0 = 0.5f * v0 * (1.f + erff(v0 * 0.70710678118654752f));
                    v1 = 0.5f * v1 * (1.f + erff(v1 * 0.70710678118654752f));
                }
                size_t base = (size_t)cO + (size_t)row * ldC + col;
                if (C) *(float2*)(C + base) = make_float2(v0, v1);
                if (Ch) *(__half2*)(Ch + base) =
                    __halves2half2(__float2half(v0), __float2half(v1));
            }
        }
    }
}

// ---------------- fused attention: softmax(qk^T + bias) @ V (validated R14) -----
__global__ void __launch_bounds__(256) fused_attn(
    const hf* __restrict__ qkv, const hf* __restrict__ vt,
    const hf* __restrict__ c2p, const hf* __restrict__ p2c,
    const float* __restrict__ mask, hf* __restrict__ ctx)
{
    extern __shared__ char smem_raw[];
    uint32_t sbase = smem_u32(smem_raw);
    float* factorArr = (float*)(smem_raw + 65536);
    float* linvArr   = (float*)(smem_raw + 66048);

    int tid = threadIdx.x, lane = tid & 31, wid = tid >> 5;
    int quad = lane >> 2, l4 = lane & 3;
    int q0 = blockIdx.x * 128, bh = blockIdx.y;
    int b = bh >> 4, h = bh & 15;
    const float scale = 0.07216878364870323f;

    const hf* qsrc = qkv + (size_t)(b*SS + q0) * (3*DD) + h*64;
    const hf* ksrc = qkv + (size_t)(b*SS) * (3*DD) + DD + h*64;
    const hf* vsrc = vt  + (size_t)bh * 64 * SS;
    const hf* c2bh = c2p + (size_t)bh * SS * PP;
    const hf* p2bh = p2c + (size_t)bh * SS * PP;
    const float* mk = mask + b * SS;

    for (int i = tid; i < 1024; i += 256) {
        int r = i >> 3, c = i & 7;
        cpa16(sbase + r*128 + ((c^(r&7))<<4), qsrc + (size_t)r*(3*DD) + c*8);
    }
    for (int i = tid; i < 512; i += 256) {
        int r = i >> 3, c = i & 7;
        cpa16(sbase + 16384 + r*128 + ((c^(r&7))<<4), ksrc + (size_t)r*(3*DD) + c*8);
    }
    cpa_commit();

    float accO[2][4][4];
    #pragma unroll
    for (int i = 0; i < 2; i++)
        #pragma unroll
        for (int j = 0; j < 4; j++)
            #pragma unroll
            for (int e = 0; e < 4; e++) accO[i][j][e] = 0.f;
    float mreg[2] = {-1e30f, -1e30f};
    float lreg[2] = {0.f, 0.f};

    int r0 = wid * 16 + quad;

    for (int t = 0; t < 16; t++) {
        asm volatile("cp.async.wait_group 0;" ::: "memory");
        __syncthreads();
        int k0 = t * 64;

        uint32_t Vb = sbase + 32768 + (t & 1) * 8192;
        for (int i = tid; i < 512; i += 256) {
            int r = i >> 3, c = i & 7;
            cpa16(Vb + r*128 + ((c^(r&7))<<4), vsrc + (size_t)r*SS + k0 + c*8);
        }
        cpa_commit();

        uint32_t Kb = sbase + 16384 + (t & 1) * 8192;
        float sacc[8][4];
        #pragma unroll
        for (int j = 0; j < 8; j++)
            #pragma unroll
            for (int e = 0; e < 4; e++) sacc[j][e] = 0.f;
        #pragma unroll
        for (int ks = 0; ks < 4; ks++) {
            uint32_t a[4], bb[8][2];
            int row = wid * 16 + (lane & 15);
            int cc = ks * 2 + (lane >> 4);
            ldm4(a, sbase + row*128 + ((cc^(row&7))<<4));
            #pragma unroll
            for (int j = 0; j < 4; j++) {
                int n = j * 16 + ((lane >> 4) << 3) + (lane & 7);
                int c2 = ks * 2 + ((lane >> 3) & 1);
                uint32_t t4[4];
                ldm4(t4, Kb + n*128 + ((c2^(n&7))<<4));
                bb[j*2][0] = t4[0];   bb[j*2][1] = t4[1];
                bb[j*2+1][0] = t4[2]; bb[j*2+1][1] = t4[3];
            }
            #pragma unroll
            for (int j = 0; j < 8; j++) mma16816(sacc[j], a, bb[j]);
        }

        if (t + 1 < 16) {
            uint32_t Kn = sbase + 16384 + ((t + 1) & 1) * 8192;
            for (int i = tid; i < 512; i += 256) {
                int r = i >> 3, c = i & 7;
                cpa16(Kn + r*128 + ((c^(r&7))<<4),
                      ksrc + (size_t)(k0 + 64 + r)*(3*DD) + c*8);
            }
            cpa_commit();
        }

        #pragma unroll
        for (int half = 0; half < 2; half++) {
            int row = r0 + half * 8;
            int qg = q0 + row;
            const hf* c2r = c2bh + (size_t)qg * PP;
            float v[16];
            float tmax = -1e30f;
            #pragma unroll
            for (int j = 0; j < 8; j++) {
                #pragma unroll
                for (int e = 0; e < 2; e++) {
                    int col = k0 + j*8 + l4*2 + e;
                    int idx = min(max(qg - col + SPAN_, 0), PP - 1);
                    float s = sacc[j][half*2 + e]
                            + __half2float(c2r[idx])
                            + __half2float(p2bh[(size_t)col * PP + idx]);
                    float vv = s * scale + (1.f - mk[col]) * -1e9f;
                    v[j*2 + e] = vv;
                    tmax = fmaxf(tmax, vv);
                }
            }
            tmax = fmaxf(tmax, __shfl_xor_sync(0xFFFFFFFFu, tmax, 1));
            tmax = fmaxf(tmax, __shfl_xor_sync(0xFFFFFFFFu, tmax, 2));
            float mnew = fmaxf(mreg[half], tmax);
            float fac = __expf(mreg[half] - mnew);
            mreg[half] = mnew;
            float sum = 0.f;
            #pragma unroll
            for (int j = 0; j < 8; j++) {
                float p0 = __expf(v[j*2]     - mnew);
                float p1 = __expf(v[j*2 + 1] - mnew);
                sum += p0 + p1;
                int col0 = j*8 + l4*2;
                int u = col0 >> 3;
                uint32_t addr = sbase + 49152 + row*128
                              + ((u ^ (row & 7)) << 4) + (col0 & 7) * 2;
                *(__half2*)(smem_raw + (addr - sbase)) =
                    __halves2half2(__float2half(p0), __float2half(p1));
            }
            sum += __shfl_xor_sync(0xFFFFFFFFu, sum, 1);
            sum += __shfl_xor_sync(0xFFFFFFFFu, sum, 2);
            lreg[half] = lreg[half] * fac + sum;
            if (l4 == 0) factorArr[row] = fac;
        }

        if (t + 1 < 16) asm volatile("cp.async.wait_group 1;" ::: "memory");
        else            asm volatile("cp.async.wait_group 0;" ::: "memory");
        __syncthreads();

        int oM = (wid & 3) * 32, oN = (wid >> 2) * 32;
        #pragma unroll
        for (int i = 0; i < 2; i++) {
            #pragma unroll
            for (int half = 0; half < 2; half++) {
                float f = factorArr[oM + i*16 + quad + half*8];
                #pragma unroll
                for (int j = 0; j < 4; j++) {
                    accO[i][j][half*2 + 0] *= f;
                    accO[i][j][half*2 + 1] *= f;
                }
            }
        }
        #pragma unroll
        for (int ks = 0; ks < 4; ks++) {
            uint32_t a[2][4], bb[4][2];
            #pragma unroll
            for (int i = 0; i < 2; i++) {
                int row = oM + i*16 + (lane & 15);
                int cc = ks * 2 + (lane >> 4);
                ldm4(a[i], sbase + 49152 + row*128 + ((cc^(row&7))<<4));
            }
            #pragma unroll
            for (int j = 0; j < 2; j++) {
                int n = oN + j*16 + ((lane >> 4) << 3) + (lane & 7);
                int c2 = ks * 2 + ((lane >> 3) & 1);
                uint32_t t4[4];
                ldm4(t4, Vb + n*128 + ((c2^(n&7))<<4));
                bb[j*2][0] = t4[0];   bb[j*2][1] = t4[1];
                bb[j*2+1][0] = t4[2]; bb[j*2+1][1] = t4[3];
            }
            #pragma unroll
            for (int i = 0; i < 2; i++)
                #pragma unroll
                for (int j = 0; j < 4; j++)
                    mma16816(accO[i][j], a[i], bb[j]);
        }
    }

    if (l4 == 0) {
        linvArr[r0]     = 1.f / lreg[0];
        linvArr[r0 + 8] = 1.f / lreg[1];
    }
    __syncthreads();

    int oM = (wid & 3) * 32, oN = (wid >> 2) * 32;
    #pragma unroll
    for (int i = 0; i < 2; i++) {
        #pragma unroll
        for (int half = 0; half < 2; half++) {
            int row = oM + i*16 + quad + half*8;
            float inv = linvArr[row];
            size_t base = ((size_t)(b*SS + q0 + row)) * DD + h*64 + oN;
            #pragma unroll
            for (int j = 0; j < 4; j++) {
                float v0 = accO[i][j][half*2 + 0] * inv;
                float v1 = accO[i][j][half*2 + 1] * inv;
                *(__half2*)(ctx + base + j*8 + l4*2) =
                    __halves2half2(__float2half(v0), __float2half(v1));
            }
        }
    }
}

// ---------------- converters -----------------------------------------------------
__global__ __launch_bounds__(256) void cvt_fp16(
    const float* __restrict__ in, hf* __restrict__ out, size_t n)
{
    size_t n4 = n >> 2;
    for (size_t i = blockIdx.x * 256ull + threadIdx.x; i < n4; i += gridDim.x * 256ull) {
        float4 v = ((const float4*)in)[i];
        hf tmp[4] = {__float2half(v.x), __float2half(v.y),
                     __float2half(v.z), __float2half(v.w)};
        ((uint2*)out)[i] = *(uint2*)tmp;
    }
}

__global__ void concat_bias(const float* bq, const float* bk, const float* bv,
                            float* out2, float* out3)
{
    int l = blockIdx.z;
    const float* a = bq + (size_t)l * DD;
    const float* b = bk + (size_t)l * DD;
    const float* c = bv + (size_t)l * DD;
    float* o3 = out3 + (size_t)l * 3 * DD;
    float* o2 = out2 + (size_t)l * 2 * DD;
    int i = blockIdx.x * 256 + threadIdx.x;
    if (i < DD) {
        o3[i] = a[i]; o3[i + DD] = b[i]; o3[i + 2*DD] = c[i];
        o2[i] = b[i]; o2[i + DD] = a[i];
    }
}

// 64x64 tile, float4 loads, 8-half vector stores
__global__ __launch_bounds__(256) void transpose_cvt(
    const float* __restrict__ in, ll inLS, hf* __restrict__ out, ll outLS,
    int K, int N)
{
    in  += (size_t)blockIdx.z * inLS;
    out += (size_t)blockIdx.z * outLS;
    __shared__ float t[64][65];
    int k0 = blockIdx.y * 64, n0 = blockIdx.x * 64;
    int tid = threadIdx.x;
    #pragma unroll
    for (int i = 0; i < 4; i++) {
        int idx = tid + i * 256;
        int r = idx >> 4, c = (idx & 15) << 2;
        float4 v = *(const float4*)(in + (size_t)(k0 + r) * N + n0 + c);
        t[r][c] = v.x; t[r][c+1] = v.y; t[r][c+2] = v.z; t[r][c+3] = v.w;
    }
    __syncthreads();
    #pragma unroll
    for (int i = 0; i < 2; i++) {
        int idx = tid + i * 256;
        int n = idx >> 3, c = (idx & 7) << 3;
        hf tmp[8];
        #pragma unroll
        for (int e = 0; e < 8; e++) tmp[e] = __float2half(t[c + e][n]);
        *(uint4*)(out + (size_t)(n0 + n) * K + k0 + c) = *(uint4*)tmp;
    }
}

__global__ void vt_cvt(const hf* __restrict__ v, int ldv, hf* __restrict__ out)
{
    __shared__ hf t[32][33];
    int bh = blockIdx.z, b = bh >> 4, h = bh & 15;
    int s0 = blockIdx.x * 32, d0 = blockIdx.y * 32;
    int tx = threadIdx.x, ty = threadIdx.y;
    for (int i = ty; i < 32; i += 8)
        t[i][tx] = v[((size_t)b * SS + s0 + i) * ldv + h * 64 + d0 + tx];
    __syncthreads();
    for (int i = ty; i < 32; i += 8)
        out[((size_t)bh * 64 + d0 + i) * SS + s0 + tx] = t[tx][i];
}

// ---------------- embedding / LN ----------------------------------------------
__global__ __launch_bounds__(256) void embed_ln(
    const int* __restrict__ ids, const int* __restrict__ segs,
    const float* __restrict__ mask, const float* __restrict__ tok,
    const float* __restrict__ seg, const float* __restrict__ g,
    const float* __restrict__ b)
{
    int row = blockIdx.x, tid = threadIdx.x;
    const float* t  = tok + (size_t)ids[row]  * DD;
    const float* sg = seg + (size_t)segs[row] * DD;
    float x[4]; float s = 0.f;
    #pragma unroll
    for (int i = 0; i < 4; i++) { int c = tid + i*256; x[i] = t[c] + sg[c]; s += x[i]; }
    __shared__ float red[256];
    red[tid] = s; __syncthreads();
    for (int o = 128; o > 0; o >>= 1) { if (tid < o) red[tid] += red[tid+o]; __syncthreads(); }
    float m = red[0] * (1.f / DD); __syncthreads();
    s = 0.f;
    #pragma unroll
    for (int i = 0; i < 4; i++) { float d = x[i] - m; s += d*d; }
    red[tid] = s; __syncthreads();
    for (int o = 128; o > 0; o >>= 1) { if (tid < o) red[tid] += red[tid+o]; __syncthreads(); }
    float inv = rsqrtf(red[0] * (1.f / DD) + 1e-12f);
    float mk = mask[row];
    #pragma unroll
    for (int i = 0; i < 4; i++) {
        int c = tid + i*256;
        float y = ((x[i] - m) * inv * g[c] + b[c]) * mk;
        size_t o = (size_t)row * DD + c;
        g_h[o] = y; hb[o] = __float2half(y);
    }
}

__global__ __launch_bounds__(256) void add_ln(
    const float* __restrict__ base, const float* __restrict__ addv,
    const float* __restrict__ g, const float* __restrict__ b,
    float* __restrict__ out)
{
    int row = blockIdx.x, tid = threadIdx.x;
    size_t off = (size_t)row * DD;
    float x[4]; float s = 0.f;
    #pragma unroll
    for (int i = 0; i < 4; i++) { int c = tid + i*256; x[i] = base[off+c] + addv[off+c]; s += x[i]; }
    __shared__ float red[256];
    red[tid] = s; __syncthreads();
    for (int o = 128; o > 0; o >>= 1) { if (tid < o) red[tid] += red[tid+o]; __syncthreads(); }
    float m = red[0] * (1.f / DD); __syncthreads();
    s = 0.f;
    #pragma unroll
    for (int i = 0; i < 4; i++) { float d = x[i] - m; s += d*d; }
    red[tid] = s; __syncthreads();
    for (int o = 128; o > 0; o >>= 1) { if (tid < o) red[tid] += red[tid+o]; __syncthreads(); }
    float inv = rsqrtf(red[0] * (1.f / DD) + 1e-12f);
    #pragma unroll
    for (int i = 0; i < 4; i++) {
        int c = tid + i*256;
        float y = (x[i] - m) * inv * g[c] + b[c];
        out[off + c] = y; hb[off + c] = __float2half(y);
    }
}

// ---------------- host --------------------------------------------------------------
extern "C" void kernel_launch(void* const* d_in, const int* in_sizes, int n_in,
                              void* d_out, int out_size)
{
    const int*   ids  = (const int*)d_in[0];
    const int*   segs = (const int*)d_in[1];
    const float* mask = (const float*)d_in[2];
    const float* tok  = (const float*)d_in[3];
    const float* seg  = (const float*)d_in[4];
    const float* elg  = (const float*)d_in[5];
    const float* elb  = (const float*)d_in[6];
    const float* rel  = (const float*)d_in[7];
    const float* Wq = (const float*)d_in[8],  *bq = (const float*)d_in[9];
    const float* Wk = (const float*)d_in[10], *bk = (const float*)d_in[11];
    const float* Wv = (const float*)d_in[12], *bv = (const float*)d_in[13];
    const float* Wo = (const float*)d_in[14], *bo = (const float*)d_in[15];
    const float* l1g = (const float*)d_in[16], *l1b = (const float*)d_in[17];
    const float* W1 = (const float*)d_in[18], *b1 = (const float*)d_in[19];
    const float* W2 = (const float*)d_in[20], *b2 = (const float*)d_in[21];
    const float* l2g = (const float*)d_in[22], *l2b = (const float*)d_in[23];

    float *h, *t2, *qb3, *pb2;
    cudaGetSymbolAddress((void**)&h,   g_h);
    cudaGetSymbolAddress((void**)&t2,  g_t2);
    cudaGetSymbolAddress((void**)&qb3, qkv_bias);
    cudaGetSymbolAddress((void**)&pb2, pos_bias);

    hf *hh,*qkv,*cx,*ff,*rl,*pos;
    hf *wqkv,*wpos,*wo_,*w1_,*w2_;
    hf *vt,*c2p,*p2c;
    cudaGetSymbolAddress((void**)&hh,  hb);
    cudaGetSymbolAddress((void**)&qkv, qkvb);  cudaGetSymbolAddress((void**)&cx, cxb);
    cudaGetSymbolAddress((void**)&ff,  ffb);   cudaGetSymbolAddress((void**)&rl, rlb);
    cudaGetSymbolAddress((void**)&pos, posb);
    cudaGetSymbolAddress((void**)&wqkv, wqkvt); cudaGetSymbolAddress((void**)&wpos, wpost);
    cudaGetSymbolAddress((void**)&wo_, wot);
    cudaGetSymbolAddress((void**)&w1_, w1t);   cudaGetSymbolAddress((void**)&w2_, w2t);
    cudaGetSymbolAddress((void**)&vt, vtb);
    cudaGetSymbolAddress((void**)&c2p, c2pb);  cudaGetSymbolAddress((void**)&p2c, p2cb);

    const int SM128 = 3 * (128*128 + 128*128);   // 98304
    const int SMATT = 66560;
    cudaFuncSetAttribute(gemm_mma<128,0>, cudaFuncAttributeMaxDynamicSharedMemorySize, SM128);
    cudaFuncSetAttribute(gemm_mma<128,1>, cudaFuncAttributeMaxDynamicSharedMemorySize, SM128);
    cudaFuncSetAttribute(fused_attn, cudaFuncAttributeMaxDynamicSharedMemorySize, SMATT);

    cudaStream_t s2;
    cudaStreamCreate(&s2);
    cudaEvent_t evPosIn, evPosOut, evQ[LL], evV[LL];
    cudaEventCreateWithFlags(&evPosIn,  cudaEventDisableTiming);
    cudaEventCreateWithFlags(&evPosOut, cudaEventDisableTiming);
    for (int l = 0; l < LL; l++) {
        cudaEventCreateWithFlags(&evQ[l], cudaEventDisableTiming);
        cudaEventCreateWithFlags(&evV[l], cudaEventDisableTiming);
    }

    dim3 tb(32, 8);
    const ll DD2 = (ll)DD * DD;
    const ll S2  = (ll)SS * SS;
    const ll SQ  = (ll)SS * 3 * DD;
    const ll POSL = (ll)PP * 2 * DD;

    // startup (legacy stream)
    cvt_fp16<<<512, 256>>>(rel, rl, (size_t)PP * DD);
    transpose_cvt<<<dim3(16,16,4), 256>>>(Wk, DD2, wpos,          2*DD2, DD, DD);
    transpose_cvt<<<dim3(16,16,4), 256>>>(Wq, DD2, wpos + DD2,    2*DD2, DD, DD);
    concat_bias<<<dim3(4,1,4), 256>>>(bq, bk, bv, pb2, qb3);
    cudaEventRecord(evPosIn, 0);

    cudaStreamWaitEvent(s2, evPosIn, 0);
    for (int l = 0; l < LL; l++)
        gemm_mma<128,0><<<dim3(16,8,1), 256, SM128, s2>>>(
            rl,DD,0,0, wpos + (size_t)l*2*DD2,DD,0,0,
            (float*)0, pos + (size_t)l*POSL, 2*DD,0,0, DD, pb2 + (size_t)l*2*DD);
    cudaEventRecord(evPosOut, s2);

    embed_ln<<<BS, 256>>>(ids, segs, mask, tok, seg, elg, elb);
    transpose_cvt<<<dim3(16,16,4), 256>>>(Wq, DD2, wqkv,          3*DD2, DD, DD);
    transpose_cvt<<<dim3(16,16,4), 256>>>(Wk, DD2, wqkv + DD2,    3*DD2, DD, DD);
    transpose_cvt<<<dim3(16,16,4), 256>>>(Wv, DD2, wqkv + 2*DD2,  3*DD2, DD, DD);
    transpose_cvt<<<dim3(16,16,4), 256>>>(Wo, DD2, wo_,           DD2,   DD, DD);
    transpose_cvt<<<dim3(64,16,4), 256>>>(W1, (ll)DD*FFD, w1_, (ll)FFD*DD, DD, FFD);
    transpose_cvt<<<dim3(16,64,4), 256>>>(W2, (ll)FFD*DD, w2_, (ll)DD*FFD, FFD, DD);

    cudaStreamWaitEvent(0, evPosOut, 0);

    for (int l = 0; l < LL; l++) {
        const hf* wqkvL = wqkv + (size_t)l * 3 * DD2;
        const hf* woL   = wo_  + (size_t)l * DD2;
        const hf* w1L   = w1_  + (size_t)l * FFD * DD;
        const hf* w2L   = w2_  + (size_t)l * DD * FFD;
        const float* qb3L = qb3 + (size_t)l * 3 * DD;
        const float* bo_ = bo + (size_t)l*DD;
        const float* b1_ = b1 + (size_t)l*FFD;
        const float* b2_ = b2 + (size_t)l*DD;
        const float* g1 = l1g + (size_t)l*DD;    const float* be1 = l1b + (size_t)l*DD;
        const float* g2 = l2g + (size_t)l*DD;    const float* be2 = l2b + (size_t)l*DD;

        gemm_mma<128,0><<<dim3(24,32,1), 256, SM128>>>(hh,DD,0,0, wqkvL,DD,0,0,
            (float*)0, qkv, 3*DD,0,0, DD, qb3L);
        cudaEventRecord(evQ[l], 0);

        const hf* q = qkv;
        const hf* k = qkv + DD;
        const hf* v = qkv + 2*DD;
        const hf* pk = pos + (size_t)l * POSL;
        const hf* pq = pk + DD;

        // s2: vt_cvt then p2c GEMM, concurrent with main's c2p GEMM
        cudaStreamWaitEvent(s2, evQ[l], 0);
        vt_cvt<<<dim3(32,2,64), tb, 0, s2>>>(v, 3*DD, vt);
        gemm_mma<128,0><<<dim3(8,8,64), 256, SM128, s2>>>(k,3*DD,SQ,64, pq,2*DD,0,64,
            (float*)0, p2c, PP,16*S2,S2, 64, (const float*)0);
        cudaEventRecord(evV[l], s2);

        gemm_mma<128,0><<<dim3(8,8,64), 256, SM128>>>(q,3*DD,SQ,64, pk,2*DD,0,64,
            (float*)0, c2p, PP,16*S2,S2, 64, (const float*)0);

        cudaStreamWaitEvent(0, evV[l], 0);
        fused_attn<<<dim3(8, 64), 256, SMATT>>>(qkv, vt, c2p, p2c, mask, cx);

        gemm_mma<128,0><<<dim3(8,32,1), 256, SM128>>>(cx,DD,0,0, woL,DD,0,0,
            t2, (hf*)0, DD,0,0, DD, bo_);
        add_ln<<<BS, 256>>>(h, t2, g1, be1, h);

        gemm_mma<128,1><<<dim3(32,32,1), 256, SM128>>>(hh,DD,0,0, w1L,DD,0,0,
            (float*)0, ff, FFD,0,0, DD, b1_);
        gemm_mma<128,0><<<dim3(8,32,1), 256, SM128>>>(ff,FFD,0,0, w2L,FFD,0,0,
            t2, (hf*)0, DD,0,0, FFD, b2_);
        add_ln<<<BS, 256>>>(h, t2, g2, be2,
                            (l == LL-1) ? (float*)d_out : h);
    }
}

// round 17
// speedup vs baseline: 1.3702x; 1.0992x over previous
#include <cuda_runtime.h>
#include <cuda_fp16.h>
#include <math.h>
#include <stdint.h>

#define BB 4
#define SS 1024
#define DD 1024
#define HH 16
#define DHH 64
#define FFD 4096
#define LL 4
#define PP 1024
#define SPAN_ 512
#define BS (BB*SS)

typedef long long ll;
typedef __half hf;

// ---------------- scratch ------------------------------------------------------
__device__ float g_h [BS*DD];
__device__ float g_t2[BS*DD];
__device__ float qkv_bias[4*3*DD];
__device__ float pos_bias[4*2*DD];

__device__ hf hb    [BS*DD];
__device__ hf qkvb  [(size_t)BS*3*DD];
__device__ hf cxb   [BS*DD];
__device__ hf ffb   [(size_t)BS*FFD];
__device__ hf rlb   [PP*DD];
__device__ hf posb  [(size_t)4*PP*2*DD];
__device__ hf wqkvt [(size_t)4*3*DD*DD];
__device__ hf wpost [(size_t)4*2*DD*DD];
__device__ hf wot   [(size_t)4*DD*DD];
__device__ hf w1t   [(size_t)4*FFD*DD];
__device__ hf w2t   [(size_t)4*DD*FFD];
__device__ hf vtb   [(size_t)BB*HH*DHH*SS];
__device__ hf c2pb  [(size_t)BB*HH*SS*PP];
__device__ hf p2cb  [(size_t)BB*HH*SS*PP];

// ---------------- helpers ------------------------------------------------------
__device__ __forceinline__ uint32_t smem_u32(const void* p) {
    uint32_t a;
    asm("{ .reg .u64 t; cvta.to.shared.u64 t, %1; cvt.u32.u64 %0, t; }" : "=r"(a) : "l"(p));
    return a;
}
__device__ __forceinline__ void cpa16(uint32_t dst, const void* src) {
    asm volatile("cp.async.cg.shared.global [%0], [%1], 16;" :: "r"(dst), "l"(src));
}
__device__ __forceinline__ void cpa_commit() { asm volatile("cp.async.commit_group;" ::: "memory"); }

__device__ __forceinline__ void ldm4(uint32_t* r, uint32_t addr) {
    asm volatile("ldmatrix.sync.aligned.m8n8.x4.shared.b16 {%0,%1,%2,%3}, [%4];"
                 : "=r"(r[0]), "=r"(r[1]), "=r"(r[2]), "=r"(r[3]) : "r"(addr));
}
__device__ __forceinline__ void mma16816(float* d, const uint32_t* a, const uint32_t* b) {
    asm volatile("mma.sync.aligned.m16n8k16.row.col.f32.f16.f16.f32 "
                 "{%0,%1,%2,%3}, {%4,%5,%6,%7}, {%8,%9}, {%0,%1,%2,%3};"
                 : "+f"(d[0]), "+f"(d[1]), "+f"(d[2]), "+f"(d[3])
                 : "r"(a[0]), "r"(a[1]), "r"(a[2]), "r"(a[3]), "r"(b[0]), "r"(b[1]));
}

// ---------------- fp16 mma.sync GEMM, 3-stage, 1 sync/chunk (validated) ----------
template <int NT, int ACT>
__global__ void __launch_bounds__(256) gemm_mma(
    const hf* __restrict__ A, int ldA, ll aSB, ll aSH,
    const hf* __restrict__ B, int ldB, ll bSB, ll bSH,
    float* __restrict__ C, hf* __restrict__ Ch,
    int ldC, ll cSB, ll cSH,
    int K, const float* __restrict__ bias)
{
    constexpr int ABY = 128 * 128;
    constexpr int BBY = NT * 128;
    constexpr int STAGE = ABY + BBY;
    constexpr int MT = (NT == 128) ? 4 : 2;
    constexpr int JT = 4;

    extern __shared__ char smem_raw[];
    uint32_t sbase = smem_u32(smem_raw);

    int tid = threadIdx.x, lane = tid & 31, wid = tid >> 5;
    int z = blockIdx.z;

    int warpM, warpN;
    if (NT == 128) { warpM = (wid & 1) * 64; warpN = (wid >> 1) * 32; }
    else           { warpM = (wid & 3) * 32; warpN = (wid >> 2) * 32; }

    const hf* Ab = A + (size_t)((ll)(z >> 4) * aSB + (ll)(z & 15) * aSH)
                     + (size_t)blockIdx.y * 128 * ldA;
    const hf* Bb = B + (size_t)((ll)(z >> 4) * bSB + (ll)(z & 15) * bSH)
                     + (size_t)blockIdx.x * NT * ldB;

    int NC = K >> 6;

    auto load_chunk = [&](int cn, int stage) {
        const hf* Ap = Ab + cn * 64;
        const hf* Bp = Bb + cn * 64;
        uint32_t Ad = sbase + stage * STAGE;
        uint32_t Bd = Ad + ABY;
        #pragma unroll
        for (int i = 0; i < 4; i++) {
            int idx = tid + i * 256;
            int r = idx >> 3, c = idx & 7;
            cpa16(Ad + r * 128 + ((c ^ (r & 7)) << 4), Ap + (size_t)r * ldA + c * 8);
        }
        #pragma unroll
        for (int i = 0; i < NT / 32; i++) {
            int idx = tid + i * 256;
            int r = idx >> 3, c = idx & 7;
            cpa16(Bd + r * 128 + ((c ^ (r & 7)) << 4), Bp + (size_t)r * ldB + c * 8);
        }
        cpa_commit();
    };

    float acc[MT][JT][4];
    #pragma unroll
    for (int i = 0; i < MT; i++)
        #pragma unroll
        for (int j = 0; j < JT; j++)
            #pragma unroll
            for (int e = 0; e < 4; e++) acc[i][j][e] = 0.f;

    load_chunk(0, 0);
    if (NC > 1) load_chunk(1, 1);

    for (int c = 0; c < NC; c++) {
        if (c + 1 < NC) asm volatile("cp.async.wait_group 1;" ::: "memory");
        else            asm volatile("cp.async.wait_group 0;" ::: "memory");
        __syncthreads();

        uint32_t Abuf = sbase + (c % 3) * STAGE;
        uint32_t Bbuf = Abuf + ABY;
        #pragma unroll
        for (int ks = 0; ks < 4; ks++) {
            uint32_t a[MT][4], b[JT][2];
            #pragma unroll
            for (int i = 0; i < MT; i++) {
                int row = warpM + i * 16 + (lane & 15);
                int cc = ks * 2 + (lane >> 4);
                ldm4(a[i], Abuf + row * 128 + (((cc ^ (row & 7)) << 4)));
            }
            #pragma unroll
            for (int j = 0; j < JT / 2; j++) {
                int n = warpN + j * 16 + ((lane >> 4) << 3) + (lane & 7);
                int cc = ks * 2 + ((lane >> 3) & 1);
                uint32_t t[4];
                ldm4(t, Bbuf + n * 128 + (((cc ^ (n & 7)) << 4)));
                b[j*2][0] = t[0];   b[j*2][1] = t[1];
                b[j*2+1][0] = t[2]; b[j*2+1][1] = t[3];
            }
            #pragma unroll
            for (int i = 0; i < MT; i++)
                #pragma unroll
                for (int j = 0; j < JT; j++)
                    mma16816(acc[i][j], a[i], b[j]);
        }
        if (c + 2 < NC) load_chunk(c + 2, (c + 2) % 3);
    }

    ll cO = (ll)(z >> 4) * cSB + (ll)(z & 15) * cSH;
    int m0 = blockIdx.y * 128, n0 = blockIdx.x * NT;
    int quad = lane >> 2, l4 = lane & 3;

    #pragma unroll
    for (int i = 0; i < MT; i++) {
        int r0 = m0 + warpM + i * 16 + quad;
        #pragma unroll
        for (int j = 0; j < JT; j++) {
            int col = n0 + warpN + j * 8 + l4 * 2;
            float b0 = 0.f, b1 = 0.f;
            if (bias) { b0 = bias[col]; b1 = bias[col + 1]; }
            #pragma unroll
            for (int half = 0; half < 2; half++) {
                int row = r0 + half * 8;
                float v0 = acc[i][j][half*2 + 0] + b0;
                float v1 = acc[i][j][half*2 + 1] + b1;
                if (ACT) {
                    v0 = 0.5f * v0 * (1.f + erff(v0 * 0.70710678118654752f));
                    v1 = 0.5f * v1 * (1.f + erff(v1 * 0.70710678118654752f));
                }
                size_t base = (size_t)cO + (size_t)row * ldC + col;
                if (C) *(float2*)(C + base) = make_float2(v0, v1);
                if (Ch) *(__half2*)(Ch + base) =
                    __halves2half2(__float2half(v0), __float2half(v1));
            }
        }
    }
}

// ---------------- fused attention, register-resident P (FA2-style) ---------------
// grid (8 q-tiles, 64 bh), block 256. Warp w owns q-rows w*16..w*16+15 end-to-end.
// SMEM: q[128x64]@0 (16K), K 2x8K @16384, V 2x8K @32768. Total 48K.
__global__ void __launch_bounds__(256) fused_attn(
    const hf* __restrict__ qkv, const hf* __restrict__ vt,
    const hf* __restrict__ c2p, const hf* __restrict__ p2c,
    const float* __restrict__ mask, hf* __restrict__ ctx)
{
    extern __shared__ char smem_raw[];
    uint32_t sbase = smem_u32(smem_raw);

    int tid = threadIdx.x, lane = tid & 31, wid = tid >> 5;
    int quad = lane >> 2, l4 = lane & 3;
    int q0 = blockIdx.x * 128, bh = blockIdx.y;
    int b = bh >> 4, h = bh & 15;
    const float scale = 0.07216878364870323f; // 1/sqrt(64*3)

    const hf* qsrc = qkv + (size_t)(b*SS + q0) * (3*DD) + h*64;
    const hf* ksrc = qkv + (size_t)(b*SS) * (3*DD) + DD + h*64;
    const hf* vsrc = vt  + (size_t)bh * 64 * SS;
    const hf* c2bh = c2p + (size_t)bh * SS * PP;
    const hf* p2bh = p2c + (size_t)bh * SS * PP;
    const float* mk = mask + b * SS;

    // load q tile + K0 + V0 (one commit group)
    for (int i = tid; i < 1024; i += 256) {
        int r = i >> 3, c = i & 7;
        cpa16(sbase + r*128 + ((c^(r&7))<<4), qsrc + (size_t)r*(3*DD) + c*8);
    }
    for (int i = tid; i < 512; i += 256) {
        int r = i >> 3, c = i & 7;
        cpa16(sbase + 16384 + r*128 + ((c^(r&7))<<4), ksrc + (size_t)r*(3*DD) + c*8);
        cpa16(sbase + 32768 + r*128 + ((c^(r&7))<<4), vsrc + (size_t)r*SS + c*8);
    }
    cpa_commit();

    float accO[8][4];
    #pragma unroll
    for (int j = 0; j < 8; j++)
        #pragma unroll
        for (int e = 0; e < 4; e++) accO[j][e] = 0.f;
    float mreg[2] = {-1e30f, -1e30f};
    float lreg[2] = {0.f, 0.f};

    for (int t = 0; t < 16; t++) {
        asm volatile("cp.async.wait_group 0;" ::: "memory");
        __syncthreads();
        int k0 = t * 64;

        // prefetch K(t+1), V(t+1)
        if (t + 1 < 16) {
            uint32_t Kn = sbase + 16384 + ((t + 1) & 1) * 8192;
            uint32_t Vn = sbase + 32768 + ((t + 1) & 1) * 8192;
            for (int i = tid; i < 512; i += 256) {
                int r = i >> 3, c = i & 7;
                cpa16(Kn + r*128 + ((c^(r&7))<<4),
                      ksrc + (size_t)(k0 + 64 + r)*(3*DD) + c*8);
                cpa16(Vn + r*128 + ((c^(r&7))<<4),
                      vsrc + (size_t)r*SS + k0 + 64 + c*8);
            }
            cpa_commit();
        }

        uint32_t Kb = sbase + 16384 + (t & 1) * 8192;
        uint32_t Vb = sbase + 32768 + (t & 1) * 8192;

        // ---- S = q(16 warp rows) @ K^T (64 cols), K = 64 ----
        float sacc[8][4];
        #pragma unroll
        for (int j = 0; j < 8; j++)
            #pragma unroll
            for (int e = 0; e < 4; e++) sacc[j][e] = 0.f;
        #pragma unroll
        for (int ks = 0; ks < 4; ks++) {
            uint32_t a[4], bb[8][2];
            int row = wid * 16 + (lane & 15);
            int cc = ks * 2 + (lane >> 4);
            ldm4(a, sbase + row*128 + ((cc^(row&7))<<4));
            #pragma unroll
            for (int j = 0; j < 4; j++) {
                int n = j * 16 + ((lane >> 4) << 3) + (lane & 7);
                int c2 = ks * 2 + ((lane >> 3) & 1);
                uint32_t t4[4];
                ldm4(t4, Kb + n*128 + ((c2^(n&7))<<4));
                bb[j*2][0] = t4[0];   bb[j*2][1] = t4[1];
                bb[j*2+1][0] = t4[2]; bb[j*2+1][1] = t4[3];
            }
            #pragma unroll
            for (int j = 0; j < 8; j++) mma16816(sacc[j], a, bb[j]);
        }

        // ---- online softmax in registers; build P fragments ----
        uint32_t p01[8], p23[8];   // per n-tile: half2(c0,c1) rows quad; half2(c2,c3) rows quad+8
        float fac[2];
        #pragma unroll
        for (int half = 0; half < 2; half++) {
            int row = wid * 16 + quad + half * 8;
            int qg = q0 + row;
            const hf* c2r = c2bh + (size_t)qg * PP;
            float v[16];
            float tmax = -1e30f;
            #pragma unroll
            for (int j = 0; j < 8; j++) {
                #pragma unroll
                for (int e = 0; e < 2; e++) {
                    int col = k0 + j*8 + l4*2 + e;
                    int idx = min(max(qg - col + SPAN_, 0), PP - 1);
                    float s = sacc[j][half*2 + e]
                            + __half2float(c2r[idx])
                            + __half2float(p2bh[(size_t)col * PP + idx]);
                    float vv = s * scale + (1.f - mk[col]) * -1e9f;
                    v[j*2 + e] = vv;
                    tmax = fmaxf(tmax, vv);
                }
            }
            tmax = fmaxf(tmax, __shfl_xor_sync(0xFFFFFFFFu, tmax, 1));
            tmax = fmaxf(tmax, __shfl_xor_sync(0xFFFFFFFFu, tmax, 2));
            float mnew = fmaxf(mreg[half], tmax);
            fac[half] = __expf(mreg[half] - mnew);
            mreg[half] = mnew;
            float sum = 0.f;
            #pragma unroll
            for (int j = 0; j < 8; j++) {
                float pa = __expf(v[j*2]     - mnew);
                float pb = __expf(v[j*2 + 1] - mnew);
                sum += pa + pb;
                __half2 pk2 = __floats2half2_rn(pa, pb);
                if (half == 0) p01[j] = *(uint32_t*)&pk2;
                else           p23[j] = *(uint32_t*)&pk2;
            }
            sum += __shfl_xor_sync(0xFFFFFFFFu, sum, 1);
            sum += __shfl_xor_sync(0xFFFFFFFFu, sum, 2);
            lreg[half] = lreg[half] * fac[half] + sum;
        }

        // ---- O = O*fac + P @ V^T (register-resident P) ----
        #pragma unroll
        for (int j = 0; j < 8; j++) {
            accO[j][0] *= fac[0]; accO[j][1] *= fac[0];
            accO[j][2] *= fac[1]; accO[j][3] *= fac[1];
        }
        #pragma unroll
        for (int ks = 0; ks < 4; ks++) {
            uint32_t a[4] = { p01[2*ks], p23[2*ks], p01[2*ks+1], p23[2*ks+1] };
            uint32_t bb[8][2];
            #pragma unroll
            for (int j = 0; j < 4; j++) {
                int n = j * 16 + ((lane >> 4) << 3) + (lane & 7);
                int c2 = ks * 2 + ((lane >> 3) & 1);
                uint32_t t4[4];
                ldm4(t4, Vb + n*128 + ((c2^(n&7))<<4));
                bb[j*2][0] = t4[0];   bb[j*2][1] = t4[1];
                bb[j*2+1][0] = t4[2]; bb[j*2+1][1] = t4[3];
            }
            #pragma unroll
            for (int j = 0; j < 8; j++) mma16816(accO[j], a, bb[j]);
        }
    }

    // ---- epilogue: normalize and store ----
    #pragma unroll
    for (int half = 0; half < 2; half++) {
        int row = wid * 16 + quad + half * 8;
        float inv = 1.f / lreg[half];
        size_t base = ((size_t)(b*SS + q0 + row)) * DD + h*64;
        #pragma unroll
        for (int j = 0; j < 8; j++) {
            float v0 = accO[j][half*2 + 0] * inv;
            float v1 = accO[j][half*2 + 1] * inv;
            *(__half2*)(ctx + base + j*8 + l4*2) =
                __halves2half2(__float2half(v0), __float2half(v1));
        }
    }
}

// ---------------- converters -----------------------------------------------------
__global__ __launch_bounds__(256) void cvt_fp16(
    const float* __restrict__ in, hf* __restrict__ out, size_t n)
{
    size_t n4 = n >> 2;
    for (size_t i = blockIdx.x * 256ull + threadIdx.x; i < n4; i += gridDim.x * 256ull) {
        float4 v = ((const float4*)in)[i];
        hf tmp[4] = {__float2half(v.x), __float2half(v.y),
                     __float2half(v.z), __float2half(v.w)};
        ((uint2*)out)[i] = *(uint2*)tmp;
    }
}

__global__ void concat_bias(const float* bq, const float* bk, const float* bv,
                            float* out2, float* out3)
{
    int l = blockIdx.z;
    const float* a = bq + (size_t)l * DD;
    const float* b = bk + (size_t)l * DD;
    const float* c = bv + (size_t)l * DD;
    float* o3 = out3 + (size_t)l * 3 * DD;
    float* o2 = out2 + (size_t)l * 2 * DD;
    int i = blockIdx.x * 256 + threadIdx.x;
    if (i < DD) {
        o3[i] = a[i]; o3[i + DD] = b[i]; o3[i + 2*DD] = c[i];
        o2[i] = b[i]; o2[i + DD] = a[i];
    }
}

// 64x64 tile, float4 loads, 8-half vector stores
__global__ __launch_bounds__(256) void transpose_cvt(
    const float* __restrict__ in, ll inLS, hf* __restrict__ out, ll outLS,
    int K, int N)
{
    in  += (size_t)blockIdx.z * inLS;
    out += (size_t)blockIdx.z * outLS;
    __shared__ float t[64][65];
    int k0 = blockIdx.y * 64, n0 = blockIdx.x * 64;
    int tid = threadIdx.x;
    #pragma unroll
    for (int i = 0; i < 4; i++) {
        int idx = tid + i * 256;
        int r = idx >> 4, c = (idx & 15) << 2;
        float4 v = *(const float4*)(in + (size_t)(k0 + r) * N + n0 + c);
        t[r][c] = v.x; t[r][c+1] = v.y; t[r][c+2] = v.z; t[r][c+3] = v.w;
    }
    __syncthreads();
    #pragma unroll
    for (int i = 0; i < 2; i++) {
        int idx = tid + i * 256;
        int n = idx >> 3, c = (idx & 7) << 3;
        hf tmp[8];
        #pragma unroll
        for (int e = 0; e < 8; e++) tmp[e] = __float2half(t[c + e][n]);
        *(uint4*)(out + (size_t)(n0 + n) * K + k0 + c) = *(uint4*)tmp;
    }
}

__global__ void vt_cvt(const hf* __restrict__ v, int ldv, hf* __restrict__ out)
{
    __shared__ hf t[32][33];
    int bh = blockIdx.z, b = bh >> 4, h = bh & 15;
    int s0 = blockIdx.x * 32, d0 = blockIdx.y * 32;
    int tx = threadIdx.x, ty = threadIdx.y;
    for (int i = ty; i < 32; i += 8)
        t[i][tx] = v[((size_t)b * SS + s0 + i) * ldv + h * 64 + d0 + tx];
    __syncthreads();
    for (int i = ty; i < 32; i += 8)
        out[((size_t)bh * 64 + d0 + i) * SS + s0 + tx] = t[tx][i];
}

// ---------------- embedding / LN ----------------------------------------------
__global__ __launch_bounds__(256) void embed_ln(
    const int* __restrict__ ids, const int* __restrict__ segs,
    const float* __restrict__ mask, const float* __restrict__ tok,
    const float* __restrict__ seg, const float* __restrict__ g,
    const float* __restrict__ b)
{
    int row = blockIdx.x, tid = threadIdx.x;
    const float* t  = tok + (size_t)ids[row]  * DD;
    const float* sg = seg + (size_t)segs[row] * DD;
    float x[4]; float s = 0.f;
    #pragma unroll
    for (int i = 0; i < 4; i++) { int c = tid + i*256; x[i] = t[c] + sg[c]; s += x[i]; }
    __shared__ float red[256];
    red[tid] = s; __syncthreads();
    for (int o = 128; o > 0; o >>= 1) { if (tid < o) red[tid] += red[tid+o]; __syncthreads(); }
    float m = red[0] * (1.f / DD); __syncthreads();
    s = 0.f;
    #pragma unroll
    for (int i = 0; i < 4; i++) { float d = x[i] - m; s += d*d; }
    red[tid] = s; __syncthreads();
    for (int o = 128; o > 0; o >>= 1) { if (tid < o) red[tid] += red[tid+o]; __syncthreads(); }
    float inv = rsqrtf(red[0] * (1.f / DD) + 1e-12f);
    float mk = mask[row];
    #pragma unroll
    for (int i = 0; i < 4; i++) {
        int c = tid + i*256;
        float y = ((x[i] - m) * inv * g[c] + b[c]) * mk;
        size_t o = (size_t)row * DD + c;
        g_h[o] = y; hb[o] = __float2half(y);
    }
}

__global__ __launch_bounds__(256) void add_ln(
    const float* __restrict__ base, const float* __restrict__ addv,
    const float* __restrict__ g, const float* __restrict__ b,
    float* __restrict__ out)
{
    int row = blockIdx.x, tid = threadIdx.x;
    size_t off = (size_t)row * DD;
    float x[4]; float s = 0.f;
    #pragma unroll
    for (int i = 0; i < 4; i++) { int c = tid + i*256; x[i] = base[off+c] + addv[off+c]; s += x[i]; }
    __shared__ float red[256];
    red[tid] = s; __syncthreads();
    for (int o = 128; o > 0; o >>= 1) { if (tid < o) red[tid] += red[tid+o]; __syncthreads(); }
    float m = red[0] * (1.f / DD); __syncthreads();
    s = 0.f;
    #pragma unroll
    for (int i = 0; i < 4; i++) { float d = x[i] - m; s += d*d; }
    red[tid] = s; __syncthreads();
    for (int o = 128; o > 0; o >>= 1) { if (tid < o) red[tid] += red[tid+o]; __syncthreads(); }
    float inv = rsqrtf(red[0] * (1.f / DD) + 1e-12f);
    #pragma unroll
    for (int i = 0; i < 4; i++) {
        int c = tid + i*256;
        float y = (x[i] - m) * inv * g[c] + b[c];
        out[off + c] = y; hb[off + c] = __float2half(y);
    }
}

// ---------------- host --------------------------------------------------------------
extern "C" void kernel_launch(void* const* d_in, const int* in_sizes, int n_in,
                              void* d_out, int out_size)
{
    const int*   ids  = (const int*)d_in[0];
    const int*   segs = (const int*)d_in[1];
    const float* mask = (const float*)d_in[2];
    const float* tok  = (const float*)d_in[3];
    const float* seg  = (const float*)d_in[4];
    const float* elg  = (const float*)d_in[5];
    const float* elb  = (const float*)d_in[6];
    const float* rel  = (const float*)d_in[7];
    const float* Wq = (const float*)d_in[8],  *bq = (const float*)d_in[9];
    const float* Wk = (const float*)d_in[10], *bk = (const float*)d_in[11];
    const float* Wv = (const float*)d_in[12], *bv = (const float*)d_in[13];
    const float* Wo = (const float*)d_in[14], *bo = (const float*)d_in[15];
    const float* l1g = (const float*)d_in[16], *l1b = (const float*)d_in[17];
    const float* W1 = (const float*)d_in[18], *b1 = (const float*)d_in[19];
    const float* W2 = (const float*)d_in[20], *b2 = (const float*)d_in[21];
    const float* l2g = (const float*)d_in[22], *l2b = (const float*)d_in[23];

    float *h, *t2, *qb3, *pb2;
    cudaGetSymbolAddress((void**)&h,   g_h);
    cudaGetSymbolAddress((void**)&t2,  g_t2);
    cudaGetSymbolAddress((void**)&qb3, qkv_bias);
    cudaGetSymbolAddress((void**)&pb2, pos_bias);

    hf *hh,*qkv,*cx,*ff,*rl,*pos;
    hf *wqkv,*wpos,*wo_,*w1_,*w2_;
    hf *vt,*c2p,*p2c;
    cudaGetSymbolAddress((void**)&hh,  hb);
    cudaGetSymbolAddress((void**)&qkv, qkvb);  cudaGetSymbolAddress((void**)&cx, cxb);
    cudaGetSymbolAddress((void**)&ff,  ffb);   cudaGetSymbolAddress((void**)&rl, rlb);
    cudaGetSymbolAddress((void**)&pos, posb);
    cudaGetSymbolAddress((void**)&wqkv, wqkvt); cudaGetSymbolAddress((void**)&wpos, wpost);
    cudaGetSymbolAddress((void**)&wo_, wot);
    cudaGetSymbolAddress((void**)&w1_, w1t);   cudaGetSymbolAddress((void**)&w2_, w2t);
    cudaGetSymbolAddress((void**)&vt, vtb);
    cudaGetSymbolAddress((void**)&c2p, c2pb);  cudaGetSymbolAddress((void**)&p2c, p2cb);

    const int SM128 = 3 * (128*128 + 128*128);   // 98304
    const int SMATT = 49152;
    cudaFuncSetAttribute(gemm_mma<128,0>, cudaFuncAttributeMaxDynamicSharedMemorySize, SM128);
    cudaFuncSetAttribute(gemm_mma<128,1>, cudaFuncAttributeMaxDynamicSharedMemorySize, SM128);
    cudaFuncSetAttribute(fused_attn, cudaFuncAttributeMaxDynamicSharedMemorySize, SMATT);

    cudaStream_t s2;
    cudaStreamCreate(&s2);
    cudaEvent_t evPosIn, evPosOut, evQ[LL], evV[LL];
    cudaEventCreateWithFlags(&evPosIn,  cudaEventDisableTiming);
    cudaEventCreateWithFlags(&evPosOut, cudaEventDisableTiming);
    for (int l = 0; l < LL; l++) {
        cudaEventCreateWithFlags(&evQ[l], cudaEventDisableTiming);
        cudaEventCreateWithFlags(&evV[l], cudaEventDisableTiming);
    }

    dim3 tb(32, 8);
    const ll DD2 = (ll)DD * DD;
    const ll S2  = (ll)SS * SS;
    const ll SQ  = (ll)SS * 3 * DD;
    const ll POSL = (ll)PP * 2 * DD;

    // startup (legacy stream)
    cvt_fp16<<<512, 256>>>(rel, rl, (size_t)PP * DD);
    transpose_cvt<<<dim3(16,16,4), 256>>>(Wk, DD2, wpos,          2*DD2, DD, DD);
    transpose_cvt<<<dim3(16,16,4), 256>>>(Wq, DD2, wpos + DD2,    2*DD2, DD, DD);
    concat_bias<<<dim3(4,1,4), 256>>>(bq, bk, bv, pb2, qb3);
    cudaEventRecord(evPosIn, 0);

    cudaStreamWaitEvent(s2, evPosIn, 0);
    for (int l = 0; l < LL; l++)
        gemm_mma<128,0><<<dim3(16,8,1), 256, SM128, s2>>>(
            rl,DD,0,0, wpos + (size_t)l*2*DD2,DD,0,0,
            (float*)0, pos + (size_t)l*POSL, 2*DD,0,0, DD, pb2 + (size_t)l*2*DD);
    cudaEventRecord(evPosOut, s2);

    embed_ln<<<BS, 256>>>(ids, segs, mask, tok, seg, elg, elb);
    transpose_cvt<<<dim3(16,16,4), 256>>>(Wq, DD2, wqkv,          3*DD2, DD, DD);
    transpose_cvt<<<dim3(16,16,4), 256>>>(Wk, DD2, wqkv + DD2,    3*DD2, DD, DD);
    transpose_cvt<<<dim3(16,16,4), 256>>>(Wv, DD2, wqkv + 2*DD2,  3*DD2, DD, DD);
    transpose_cvt<<<dim3(16,16,4), 256>>>(Wo, DD2, wo_,           DD2,   DD, DD);
    transpose_cvt<<<dim3(64,16,4), 256>>>(W1, (ll)DD*FFD, w1_, (ll)FFD*DD, DD, FFD);
    transpose_cvt<<<dim3(16,64,4), 256>>>(W2, (ll)FFD*DD, w2_, (ll)DD*FFD, FFD, DD);

    cudaStreamWaitEvent(0, evPosOut, 0);

    for (int l = 0; l < LL; l++) {
        const hf* wqkvL = wqkv + (size_t)l * 3 * DD2;
        const hf* woL   = wo_  + (size_t)l * DD2;
        const hf* w1L   = w1_  + (size_t)l * FFD * DD;
        const hf* w2L   = w2_  + (size_t)l * DD * FFD;
        const float* qb3L = qb3 + (size_t)l * 3 * DD;
        const float* bo_ = bo + (size_t)l*DD;
        const float* b1_ = b1 + (size_t)l*FFD;
        const float* b2_ = b2 + (size_t)l*DD;
        const float* g1 = l1g + (size_t)l*DD;    const float* be1 = l1b + (size_t)l*DD;
        const float* g2 = l2g + (size_t)l*DD;    const float* be2 = l2b + (size_t)l*DD;

        gemm_mma<128,0><<<dim3(24,32,1), 256, SM128>>>(hh,DD,0,0, wqkvL,DD,0,0,
            (float*)0, qkv, 3*DD,0,0, DD, qb3L);
        cudaEventRecord(evQ[l], 0);

        const hf* q = qkv;
        const hf* k = qkv + DD;
        const hf* v = qkv + 2*DD;
        const hf* pk = pos + (size_t)l * POSL;
        const hf* pq = pk + DD;

        cudaStreamWaitEvent(s2, evQ[l], 0);
        vt_cvt<<<dim3(32,2,64), tb, 0, s2>>>(v, 3*DD, vt);
        gemm_mma<128,0><<<dim3(8,8,64), 256, SM128, s2>>>(k,3*DD,SQ,64, pq,2*DD,0,64,
            (float*)0, p2c, PP,16*S2,S2, 64, (const float*)0);
        cudaEventRecord(evV[l], s2);

        gemm_mma<128,0><<<dim3(8,8,64), 256, SM128>>>(q,3*DD,SQ,64, pk,2*DD,0,64,
            (float*)0, c2p, PP,16*S2,S2, 64, (const float*)0);

        cudaStreamWaitEvent(0, evV[l], 0);
        fused_attn<<<dim3(8, 64), 256, SMATT>>>(qkv, vt, c2p, p2c, mask, cx);

        gemm_mma<128,0><<<dim3(8,32,1), 256, SM128>>>(cx,DD,0,0, woL,DD,0,0,
            t2, (hf*)0, DD,0,0, DD, bo_);
        add_ln<<<BS, 256>>>(h, t2, g1, be1, h);

        gemm_mma<128,1><<<dim3(32,32,1), 256, SM128>>>(hh,DD,0,0, w1L,DD,0,0,
            (float*)0, ff, FFD,0,0, DD, b1_);
        gemm_mma<128,0><<<dim3(8,32,1), 256, SM128>>>(ff,FFD,0,0, w2L,FFD,0,0,
            t2, (hf*)0, DD,0,0, FFD, b2_);
        add_ln<<<BS, 256>>>(h, t2, g2, be2,
                            (l == LL-1) ? (float*)d_out : h);
    }
}